// round 7
// baseline (speedup 1.0000x reference)
#include <cuda_runtime.h>
#include <cuda_bf16.h>
#include <math.h>
#include <cstdint>

#define BSZ 128
#define NTREE 4095
#define NT 512

// smem bytes: A ping-pong 2x32KB @0; idx 2x512B @65536; B frags 80KB @66560
#define A_OFF 0
#define IDX_OFF 65536
#define B_OFF 66560
#define SMEM_TOTAL (B_OFF + 81920)

__device__ __nv_bfloat16 g_h[2][(size_t)BSZ * 2048 * 64];
__device__ __nv_bfloat16 g_c[2][(size_t)BSZ * 2048 * 64];
__device__ uint32_t g_Bfrag[20480];   // bf16x2 fragment-ordered U
__device__ uint32_t g_Wxb[20480];     // bf16x2 Wx table [idx][g][colpair]

__device__ __forceinline__ uint32_t smem_u32(const void* p) {
    uint32_t a;
    asm("{ .reg .u64 t; cvta.to.shared.u64 t, %1; cvt.u32.u64 %0, t; }" : "=r"(a) : "l"(p));
    return a;
}
__device__ __forceinline__ float tanhap(float x) {
    float y;
    asm("tanh.approx.f32 %0, %1;" : "=f"(y) : "f"(x));
    return y;
}
__device__ __forceinline__ float sigap(float x) {
    return fmaf(tanhap(0.5f * x), 0.5f, 0.5f);
}
__device__ __forceinline__ uint32_t pbf2(float lo, float hi) {
    uint32_t r;
    asm("cvt.rn.bf16x2.f32 %0, %1, %2;" : "=r"(r) : "f"(hi), "f"(lo));
    return r;
}
__device__ __forceinline__ void ubf2(uint32_t p, float& lo, float& hi) {
    __nv_bfloat162 b = *(__nv_bfloat162*)&p;
    lo = __bfloat162float(b.x);
    hi = __bfloat162float(b.y);
}
__device__ __forceinline__ void mma_bf16(float c[4], uint32_t a0, uint32_t a1,
                                         uint32_t a2, uint32_t a3,
                                         uint32_t b0, uint32_t b1) {
    asm volatile(
        "mma.sync.aligned.m16n8k16.row.col.f32.bf16.bf16.f32 "
        "{%0,%1,%2,%3}, {%4,%5,%6,%7}, {%8,%9}, {%0,%1,%2,%3};"
        : "+f"(c[0]), "+f"(c[1]), "+f"(c[2]), "+f"(c[3])
        : "r"(a0), "r"(a1), "r"(a2), "r"(a3), "r"(b0), "r"(b1));
}

// ---------------- prep: U fragments + Wx bf16 table
__global__ void prep_kernel(const float* __restrict__ Ua, const float* __restrict__ Ub,
                            const float* __restrict__ Wx) {
    int id = blockIdx.x * blockDim.x + threadIdx.x;   // 20480
    if (id >= 20480) return;
    {   // U: [g][wn][ks][lane][j]
        int j = id & 1;
        int lane = (id >> 1) & 31;
        int ks = (id >> 6) & 7;
        int wn = (id >> 9) & 7;
        int g = id >> 12;
        int k0 = ks * 16 + (lane & 3) * 2 + j * 8;
        int n = g * 64 + wn * 8 + (lane >> 2);
        float v0 = (k0 < 64) ? Ua[k0 * 320 + n] : Ub[(k0 - 64) * 320 + n];
        float v1 = (k0 + 1 < 64) ? Ua[(k0 + 1) * 320 + n] : Ub[(k0 + 1 - 64) * 320 + n];
        g_Bfrag[id] = pbf2(v0, v1);
    }
    {   // Wx: [idx][g][jp] = cols (g*64+2jp, +1)
        int idx = id / 160;
        int rem = id - idx * 160;
        int g = rem >> 5, jp = rem & 31;
        const float* w = Wx + idx * 320 + g * 64 + 2 * jp;
        g_Wxb[id] = pbf2(w[0], w[1]);
    }
}

// ---------------- leaf level d=11
__global__ void leaf_kernel(const int* __restrict__ x_idx,
                            const float* __restrict__ bt) {
    int id = blockIdx.x * blockDim.x + threadIdx.x;   // B*2048*16
    int q = id & 15;
    int m = id >> 4;
    int b = m >> 11, jl = m & 2047;
    int idx = x_idx[b * NTREE + 2047 + jl];
    const uint32_t* w = g_Wxb + idx * 160 + q * 2;
    int c4 = q * 4;
    uint2 wi = *(const uint2*)(w);
    uint2 wo = *(const uint2*)(w + 96);
    uint2 wu = *(const uint2*)(w + 128);
    float4 bi = *(const float4*)(bt + c4);
    float4 bo = *(const float4*)(bt + 192 + c4);
    float4 bu = *(const float4*)(bt + 256 + c4);
    float wif[4], wof[4], wuf[4];
    ubf2(wi.x, wif[0], wif[1]); ubf2(wi.y, wif[2], wif[3]);
    ubf2(wo.x, wof[0], wof[1]); ubf2(wo.y, wof[2], wof[3]);
    ubf2(wu.x, wuf[0], wuf[1]); ubf2(wu.y, wuf[2], wuf[3]);
    float cv[4], hv[4];
#pragma unroll
    for (int e = 0; e < 4; ++e) {
        float zi = wif[e] + ((const float*)&bi)[e];
        float zo = wof[e] + ((const float*)&bo)[e];
        float zu = wuf[e] + ((const float*)&bu)[e];
        cv[e] = sigap(zi) * tanhap(zu);
        hv[e] = sigap(zo) * tanhap(cv[e]);
    }
    *(uint2*)(g_h[1] + (size_t)m * 64 + c4) = make_uint2(pbf2(hv[0], hv[1]), pbf2(hv[2], hv[3]));
    *(uint2*)(g_c[1] + (size_t)m * 64 + c4) = make_uint2(pbf2(cv[0], cv[1]), pbf2(cv[2], cv[3]));
}

// ---------------- tile pieces (512 threads, 128-row tiles)
__device__ __forceinline__ void fill_a(char* smem, int abase,
                                       const __nv_bfloat16* __restrict__ asrc,
                                       const int* __restrict__ idxp, int ibase,
                                       int nvalid) {
    int tid = threadIdx.x;
    const uint4* src = (const uint4*)asrc;
#pragma unroll
    for (int i = 0; i < 4; ++i) {
        int f = tid + i * NT;             // 0..2047
        int row = f >> 4, c = f & 15;
        uint4 v = make_uint4(0, 0, 0, 0);
        if (row < nvalid) v = src[f];
        *(uint4*)(smem + abase + row * 256 + ((c ^ (row & 7)) << 4)) = v;
    }
    if (tid < 128)
        *(int*)(smem + ibase + tid * 4) = (tid < nvalid) ? idxp[tid] : 0;
}

__device__ __forceinline__ void do_mma(char* smem, uint32_t sA, float acc[4][5][4],
                                       int nvalid, int wm, int wn, int lane) {
    const int row_local = (lane & 7) | (((lane >> 3) & 1) << 3);
    const int hi = (lane >> 4) & 1;
#pragma unroll
    for (int ks = 0; ks < 8; ++ks) {
        uint2 bf[5];
#pragma unroll
        for (int g = 0; g < 5; ++g)
            bf[g] = *(const uint2*)(smem + B_OFF + ((((g * 8 + wn) * 8 + ks) * 32 + lane) << 3));
        int c = ks * 2 + hi;
#pragma unroll
        for (int mfl = 0; mfl < 4; ++mfl) {
            int mf = wm * 4 + mfl;
            if (mf * 16 < nvalid) {
                uint32_t addr = sA + (mf * 16 + row_local) * 256 + ((c ^ (lane & 7)) << 4);
                uint32_t a0, a1, a2, a3;
                asm volatile("ldmatrix.sync.aligned.m8n8.x4.shared.b16 {%0,%1,%2,%3}, [%4];"
                             : "=r"(a0), "=r"(a1), "=r"(a2), "=r"(a3) : "r"(addr));
#pragma unroll
                for (int g = 0; g < 5; ++g)
                    mma_bf16(acc[mfl][g], a0, a1, a2, a3, bf[g].x, bf[g].y);
            }
        }
    }
}

// in-register epilogue: each lane owns (row, colpair) for all 5 gates
__device__ __forceinline__ void epilogue_r(char* smem, int ibase, float acc[4][5][4],
                                           int nvalid,
                                           const __nv_bfloat16* __restrict__ csrc,
                                           __nv_bfloat16* __restrict__ houtp,
                                           __nv_bfloat16* __restrict__ coutp,
                                           const float2 barr[5], int wm, int jp, int lane) {
#pragma unroll
    for (int mfl = 0; mfl < 4; ++mfl) {
#pragma unroll
        for (int half = 0; half < 2; ++half) {
            int rloc = wm * 64 + mfl * 16 + half * 8 + (lane >> 2);
            if (rloc < nvalid) {
                int idx = *(const int*)(smem + ibase + rloc * 4);
                const uint32_t* w = g_Wxb + idx * 160 + jp;
                float wx[5][2];
#pragma unroll
                for (int g = 0; g < 5; ++g) ubf2(w[g * 32], wx[g][0], wx[g][1]);
                float ca0, ca1, cb0, cb1;
                ubf2(*(const uint32_t*)(csrc + (size_t)rloc * 128 + 2 * jp), ca0, ca1);
                ubf2(*(const uint32_t*)(csrc + (size_t)rloc * 128 + 64 + 2 * jp), cb0, cb1);
                int e = half * 2;
                float zi0 = acc[mfl][0][e] + wx[0][0] + barr[0].x;
                float zi1 = acc[mfl][0][e + 1] + wx[0][1] + barr[0].y;
                float za0 = acc[mfl][1][e] + wx[1][0] + barr[1].x;
                float za1 = acc[mfl][1][e + 1] + wx[1][1] + barr[1].y;
                float zb0 = acc[mfl][2][e] + wx[2][0] + barr[2].x;
                float zb1 = acc[mfl][2][e + 1] + wx[2][1] + barr[2].y;
                float zo0 = acc[mfl][3][e] + wx[3][0] + barr[3].x;
                float zo1 = acc[mfl][3][e + 1] + wx[3][1] + barr[3].y;
                float zu0 = acc[mfl][4][e] + wx[4][0] + barr[4].x;
                float zu1 = acc[mfl][4][e + 1] + wx[4][1] + barr[4].y;
                float c0 = sigap(zi0) * tanhap(zu0) + sigap(za0) * ca0 + sigap(zb0) * cb0;
                float c1 = sigap(zi1) * tanhap(zu1) + sigap(za1) * ca1 + sigap(zb1) * cb1;
                float h0 = sigap(zo0) * tanhap(c0);
                float h1 = sigap(zo1) * tanhap(c1);
                *(uint32_t*)(houtp + (size_t)rloc * 64 + 2 * jp) = pbf2(h0, h1);
                *(uint32_t*)(coutp + (size_t)rloc * 64 + 2 * jp) = pbf2(c0, c1);
            }
        }
    }
}

__device__ __forceinline__ void load_common(char* smem, const float* bt, float2 barr[5],
                                            int jp) {
    int tid = threadIdx.x;
    const uint4* src = (const uint4*)g_Bfrag;
    uint4* dst = (uint4*)(smem + B_OFF);
#pragma unroll
    for (int i = 0; i < 10; ++i) dst[tid + i * NT] = src[tid + i * NT];
#pragma unroll
    for (int g = 0; g < 5; ++g) barr[g] = *(const float2*)(bt + g * 64 + 2 * jp);
}

// ---------------- big levels d = 10, 9 (double-buffered A, one bar per tile)
__global__ void __launch_bounds__(NT, 1)
level_mma(int d, const int* __restrict__ x_idx, const float* __restrict__ bt,
          int pin, int pout) {
    extern __shared__ char smem[];
    uint32_t sb = smem_u32(smem);
    const int tid = threadIdx.x;
    const int lane = tid & 31, wid = tid >> 5;
    const int wm = wid >> 3, wn = wid & 7;
    const int jp = wn * 4 + (lane & 3);
    float2 barr[5];
    load_common(smem, bt, barr, jp);
    const __nv_bfloat16* hc = g_h[pin];
    const __nv_bfloat16* cc = g_c[pin];
    __nv_bfloat16* ho = g_h[pout];
    __nv_bfloat16* co = g_c[pout];
    const int n = 1 << d;          // tiles of 128 rows
    int t = blockIdx.x;
    int p = 0;
    if (t < n)
        fill_a(smem, p * 32768, hc + (size_t)(t << 7) * 128,
               x_idx + ((t << 7) >> d) * NTREE + (n - 1) + ((t << 7) & (n - 1)),
               IDX_OFF + p * 512, 128);
    __syncthreads();
    for (; t < n; t += gridDim.x) {
        int m0 = t << 7;
        float acc[4][5][4] = {};
        do_mma(smem, sb + p * 32768, acc, 128, wm, wn, lane);
        int nt = t + gridDim.x;
        if (nt < n)
            fill_a(smem, (p ^ 1) * 32768, hc + (size_t)(nt << 7) * 128,
                   x_idx + ((nt << 7) >> d) * NTREE + (n - 1) + ((nt << 7) & (n - 1)),
                   IDX_OFF + (p ^ 1) * 512, 128);
        __syncthreads();
        epilogue_r(smem, IDX_OFF + p * 512, acc, 128, cc + (size_t)m0 * 128,
                   ho + (size_t)m0 * 64, co + (size_t)m0 * 64, barr, wm, jp, lane);
        p ^= 1;
    }
}

// ---------------- fused top levels d = 8..0, one CTA per batch
__global__ void __launch_bounds__(NT, 1)
top_mma(const int* __restrict__ x_idx, const float* __restrict__ bt) {
    extern __shared__ char smem[];
    uint32_t sb = smem_u32(smem);
    const int tid = threadIdx.x;
    const int lane = tid & 31, wid = tid >> 5;
    const int wm = wid >> 3, wn = wid & 7;
    const int jp = wn * 4 + (lane & 3);
    float2 barr[5];
    load_common(smem, bt, barr, jp);
    __syncthreads();
    const int b = blockIdx.x;
    for (int d = 8; d >= 0; --d) {
        int n = 1 << d;
        int pin = (d + 1) & 1, pout = d & 1;
        int ntile = (n + 127) >> 7;
        for (int tt = 0; tt < ntile; ++tt) {
            int m0l = tt << 7;
            int count = n - m0l < 128 ? n - m0l : 128;
            fill_a(smem, 0, g_h[pin] + (size_t)(b * 2 * n + 2 * m0l) * 64,
                   x_idx + b * NTREE + (n - 1) + m0l, IDX_OFF, count);
            __syncthreads();
            float acc[4][5][4] = {};
            do_mma(smem, sb, acc, count, wm, wn, lane);
            epilogue_r(smem, IDX_OFF, acc, count,
                       g_c[pin] + (size_t)(b * 2 * n + 2 * m0l) * 64,
                       g_h[pout] + (size_t)(b * n + m0l) * 64,
                       g_c[pout] + (size_t)(b * n + m0l) * 64, barr, wm, jp, lane);
            __syncthreads();
        }
    }
}

// ---------------- head
__global__ void head_kernel(const float* __restrict__ W1, const float* __restrict__ b1,
                            const float* __restrict__ W2, const float* __restrict__ b2,
                            const float* __restrict__ W_ih, const float* __restrict__ b_lstm,
                            const float* __restrict__ actorW, const float* __restrict__ actorb,
                            const float* __restrict__ vm, float* __restrict__ out) {
    __shared__ float sh[64], sf1[64], sfeat[128], slog[20], sinv[1];
    int b = blockIdx.x;
    int t = threadIdx.x;
    sh[t] = __bfloat162float(g_h[0][b * 64 + t]);
    __syncthreads();
    float a = 0.f;
    for (int k = 0; k < 64; ++k) a += sh[k] * W1[k * 64 + t];
    a += b1[t];
    sf1[t] = fmaxf(a, 0.f);
    __syncthreads();
    float f = 0.f;
    for (int k = 0; k < 64; ++k) f += sf1[k] * W2[k * 64 + t];
    f += b2[t];
    sfeat[t] = f;
    __syncthreads();
    float gi = 0.f, gg = 0.f, go = 0.f;
    for (int k = 0; k < 64; ++k) {
        float fk = sfeat[k];
        gi += fk * W_ih[k * 256 + t];
        gg += fk * W_ih[k * 256 + 128 + t];
        go += fk * W_ih[k * 256 + 192 + t];
    }
    gi += b_lstm[t];
    gg += b_lstm[128 + t];
    go += b_lstm[192 + t];
    float cg = (1.f / (1.f + expf(-gi))) * tanhf(gg);
    float hg = (1.f / (1.f + expf(-go))) * tanhf(cg);
    sfeat[64 + t] = hg;
    __syncthreads();
    if (t < 20) {
        float l = 0.f;
        for (int dd = 0; dd < 128; ++dd) l += sfeat[dd] * actorW[dd * 20 + t];
        l = logf(vm[t]) + l * vm[t] + actorb[t] * vm[t];
        slog[t] = l / 3.0f;
    }
    __syncthreads();
    if (t == 0) {
        float mx = slog[0];
        for (int k = 1; k < 20; ++k) mx = fmaxf(mx, slog[k]);
        float s = 0.f;
        for (int k = 0; k < 20; ++k) {
            float e = expf(slog[k] - mx);
            slog[k] = e;
            s += e;
        }
        sinv[0] = 1.f / s;
    }
    __syncthreads();
    if (t < 20) out[b * 20 + t] = slog[t] * sinv[0];
}

extern "C" void kernel_launch(void* const* d_in, const int* in_sizes, int n_in,
                              void* d_out, int out_size) {
    const int*   x_idx  = (const int*)d_in[0];
    const float* vm     = (const float*)d_in[1];
    const float* Wx     = (const float*)d_in[2];
    const float* Ua     = (const float*)d_in[3];
    const float* Ub     = (const float*)d_in[4];
    const float* bt     = (const float*)d_in[5];
    const float* W_ih   = (const float*)d_in[6];
    const float* b_lstm = (const float*)d_in[8];
    const float* W1     = (const float*)d_in[9];
    const float* b1     = (const float*)d_in[10];
    const float* W2     = (const float*)d_in[11];
    const float* b2     = (const float*)d_in[12];
    const float* actorW = (const float*)d_in[13];
    const float* actorb = (const float*)d_in[14];
    float* out = (float*)d_out;

    cudaFuncSetAttribute(level_mma, cudaFuncAttributeMaxDynamicSharedMemorySize, SMEM_TOTAL);
    cudaFuncSetAttribute(top_mma, cudaFuncAttributeMaxDynamicSharedMemorySize, SMEM_TOTAL);

    prep_kernel<<<80, 256>>>(Ua, Ub, Wx);
    leaf_kernel<<<(BSZ * 2048 * 16) / 256, 256>>>(x_idx, bt);

    for (int d = 10; d >= 9; --d) {
        int ntile = 1 << d;
        int grid = ntile < 152 ? ntile : 152;
        level_mma<<<grid, NT, SMEM_TOTAL>>>(d, x_idx, bt, (d + 1) & 1, d & 1);
    }
    top_mma<<<BSZ, NT, SMEM_TOTAL>>>(x_idx, bt);

    head_kernel<<<BSZ, 64>>>(W1, b1, W2, b2, W_ih, b_lstm, actorW, actorb, vm, out);
}

// round 8
// speedup vs baseline: 1.0403x; 1.0403x over previous
#include <cuda_runtime.h>
#include <cuda_fp16.h>
#include <math.h>
#include <cstdint>

#define BSZ 128
#define NTREE 4095
#define NT 512

// smem: A ping-pong 2x32KB @0; idx 3x512B @65536; B frags 80KB @67072
#define IDX_OFF 65536
#define B_OFF 67072
#define SMEM_TOTAL (B_OFF + 81920)

__device__ __half g_h[2][(size_t)BSZ * 2048 * 64];
__device__ __half g_c[2][(size_t)BSZ * 2048 * 64];
__device__ uint32_t g_Bfrag[20480];   // f16x2 fragment-ordered U
__device__ uint32_t g_Wxb[20480];     // f16x2 Wx table [idx][g][colpair]

__device__ __forceinline__ uint32_t smem_u32(const void* p) {
    uint32_t a;
    asm("{ .reg .u64 t; cvta.to.shared.u64 t, %1; cvt.u32.u64 %0, t; }" : "=r"(a) : "l"(p));
    return a;
}
__device__ __forceinline__ __half2 tanh2(__half2 x) {
    uint32_t r, xi = *(uint32_t*)&x;
    asm("tanh.approx.f16x2 %0, %1;" : "=r"(r) : "r"(xi));
    return *(__half2*)&r;
}
__device__ __forceinline__ __half2 sig2(__half2 x) {
    const __half2 h = __float2half2_rn(0.5f);
    return __hfma2(tanh2(__hmul2(x, h)), h, h);
}
__device__ __forceinline__ float tanhap(float x) {
    float y;
    asm("tanh.approx.f32 %0, %1;" : "=f"(y) : "f"(x));
    return y;
}
__device__ __forceinline__ void mma_f16(uint32_t d[2], uint32_t a0, uint32_t a1,
                                        uint32_t a2, uint32_t a3,
                                        uint32_t b0, uint32_t b1) {
    asm volatile(
        "mma.sync.aligned.m16n8k16.row.col.f16.f16.f16.f16 "
        "{%0,%1}, {%2,%3,%4,%5}, {%6,%7}, {%0,%1};"
        : "+r"(d[0]), "+r"(d[1])
        : "r"(a0), "r"(a1), "r"(a2), "r"(a3), "r"(b0), "r"(b1));
}

// ---------------- prep: U fragments + Wx f16 table
__global__ void prep_kernel(const float* __restrict__ Ua, const float* __restrict__ Ub,
                            const float* __restrict__ Wx) {
    int id = blockIdx.x * blockDim.x + threadIdx.x;   // 20480
    if (id >= 20480) return;
    {   // U: [g][wn][ks][lane][j]
        int j = id & 1;
        int lane = (id >> 1) & 31;
        int ks = (id >> 6) & 7;
        int wn = (id >> 9) & 7;
        int g = id >> 12;
        int k0 = ks * 16 + (lane & 3) * 2 + j * 8;
        int n = g * 64 + wn * 8 + (lane >> 2);
        float v0 = (k0 < 64) ? Ua[k0 * 320 + n] : Ub[(k0 - 64) * 320 + n];
        float v1 = (k0 + 1 < 64) ? Ua[(k0 + 1) * 320 + n] : Ub[(k0 + 1 - 64) * 320 + n];
        __half2 p = __floats2half2_rn(v0, v1);
        g_Bfrag[id] = *(uint32_t*)&p;
    }
    {   // Wx: [idx][g][jp] = cols (g*64+2jp, +1)
        int idx = id / 160;
        int rem = id - idx * 160;
        int g = rem >> 5, jp = rem & 31;
        const float* w = Wx + idx * 320 + g * 64 + 2 * jp;
        __half2 p = __floats2half2_rn(w[0], w[1]);
        g_Wxb[id] = *(uint32_t*)&p;
    }
}

// ---------------- leaf level d=11 (packed f16x2)
__global__ void leaf_kernel(const int* __restrict__ x_idx,
                            const float* __restrict__ bt) {
    int id = blockIdx.x * blockDim.x + threadIdx.x;   // B*2048*16
    int q = id & 15;
    int m = id >> 4;
    int b = m >> 11, jl = m & 2047;
    int idx = x_idx[b * NTREE + 2047 + jl];
    const __half2* w = (const __half2*)g_Wxb + idx * 160 + q * 2;
    int c4 = q * 4;
    float4 bi = *(const float4*)(bt + c4);
    float4 bo = *(const float4*)(bt + 192 + c4);
    float4 bu = *(const float4*)(bt + 256 + c4);
    __half2 cv[2], hv[2];
#pragma unroll
    for (int e = 0; e < 2; ++e) {
        __half2 zi = __hadd2(w[e], __floats2half2_rn(((float*)&bi)[2 * e], ((float*)&bi)[2 * e + 1]));
        __half2 zo = __hadd2(w[96 + e], __floats2half2_rn(((float*)&bo)[2 * e], ((float*)&bo)[2 * e + 1]));
        __half2 zu = __hadd2(w[128 + e], __floats2half2_rn(((float*)&bu)[2 * e], ((float*)&bu)[2 * e + 1]));
        cv[e] = __hmul2(sig2(zi), tanh2(zu));
        hv[e] = __hmul2(sig2(zo), tanh2(cv[e]));
    }
    *(uint2*)(g_h[1] + (size_t)m * 64 + c4) =
        make_uint2(*(uint32_t*)&hv[0], *(uint32_t*)&hv[1]);
    *(uint2*)(g_c[1] + (size_t)m * 64 + c4) =
        make_uint2(*(uint32_t*)&cv[0], *(uint32_t*)&cv[1]);
}

// ---------------- tile pieces (512 threads, 128-row tiles)
__device__ __forceinline__ void fill_a(char* smem, int abase,
                                       const __half* __restrict__ asrc,
                                       const int* __restrict__ idxp, int islot,
                                       int nvalid) {
    int tid = threadIdx.x;
    const uint4* src = (const uint4*)asrc;
#pragma unroll
    for (int i = 0; i < 4; ++i) {
        int f = tid + i * NT;             // 0..2047
        int row = f >> 4, c = f & 15;
        uint4 v = make_uint4(0, 0, 0, 0);
        if (row < nvalid) v = src[f];
        *(uint4*)(smem + abase + row * 256 + ((c ^ (row & 7)) << 4)) = v;
    }
    if (tid < 128)
        *(int*)(smem + IDX_OFF + islot * 512 + tid * 4) = (tid < nvalid) ? idxp[tid] : 0;
}

__device__ __forceinline__ void do_mma(char* smem, uint32_t sA, uint32_t acc[4][5][2],
                                       int nvalid, int wm, int wn, int lane) {
    const int row_local = (lane & 7) | (((lane >> 3) & 1) << 3);
    const int hi = (lane >> 4) & 1;
#pragma unroll
    for (int ks = 0; ks < 8; ++ks) {
        uint2 bf[5];
#pragma unroll
        for (int g = 0; g < 5; ++g)
            bf[g] = *(const uint2*)(smem + B_OFF + ((((g * 8 + wn) * 8 + ks) * 32 + lane) << 3));
        int c = ks * 2 + hi;
#pragma unroll
        for (int mfl = 0; mfl < 4; ++mfl) {
            int mf = wm * 4 + mfl;
            if (mf * 16 < nvalid) {
                uint32_t addr = sA + (mf * 16 + row_local) * 256 + ((c ^ (lane & 7)) << 4);
                uint32_t a0, a1, a2, a3;
                asm volatile("ldmatrix.sync.aligned.m8n8.x4.shared.b16 {%0,%1,%2,%3}, [%4];"
                             : "=r"(a0), "=r"(a1), "=r"(a2), "=r"(a3) : "r"(addr));
#pragma unroll
                for (int g = 0; g < 5; ++g)
                    mma_f16(acc[mfl][g], a0, a1, a2, a3, bf[g].x, bf[g].y);
            }
        }
    }
}

// packed f16x2 in-register epilogue
__device__ __forceinline__ void epilogue_h(char* smem, int islot, uint32_t acc[4][5][2],
                                           int nvalid,
                                           const __half* __restrict__ csrc,
                                           __half* __restrict__ houtp,
                                           __half* __restrict__ coutp,
                                           const __half2 bb2[5], int wm, int jp, int lane) {
#pragma unroll
    for (int mfl = 0; mfl < 4; ++mfl) {
#pragma unroll
        for (int half = 0; half < 2; ++half) {
            int rloc = wm * 64 + mfl * 16 + half * 8 + (lane >> 2);
            if (rloc < nvalid) {
                int idx = *(const int*)(smem + IDX_OFF + islot * 512 + rloc * 4);
                const __half2* w = (const __half2*)g_Wxb + idx * 160 + jp;
                __half2 z[5];
#pragma unroll
                for (int g = 0; g < 5; ++g)
                    z[g] = __hadd2(__hadd2(*(__half2*)&acc[mfl][g][half], w[g * 32]), bb2[g]);
                __half2 ca = *(const __half2*)(csrc + (size_t)rloc * 128 + 2 * jp);
                __half2 cb = *(const __half2*)(csrc + (size_t)rloc * 128 + 64 + 2 * jp);
                __half2 cn = __hfma2(sig2(z[1]), ca,
                              __hfma2(sig2(z[2]), cb,
                               __hmul2(sig2(z[0]), tanh2(z[4]))));
                __half2 hn = __hmul2(sig2(z[3]), tanh2(cn));
                *(uint32_t*)(houtp + (size_t)rloc * 64 + 2 * jp) = *(uint32_t*)&hn;
                *(uint32_t*)(coutp + (size_t)rloc * 64 + 2 * jp) = *(uint32_t*)&cn;
            }
        }
    }
}

__device__ __forceinline__ void load_common(char* smem, const float* bt, __half2 bb2[5],
                                            int jp) {
    int tid = threadIdx.x;
    const uint4* src = (const uint4*)g_Bfrag;
    uint4* dst = (uint4*)(smem + B_OFF);
#pragma unroll
    for (int i = 0; i < 10; ++i) dst[tid + i * NT] = src[tid + i * NT];
#pragma unroll
    for (int g = 0; g < 5; ++g) {
        float2 bv = *(const float2*)(bt + g * 64 + 2 * jp);
        bb2[g] = __floats2half2_rn(bv.x, bv.y);
    }
}

// ---------------- big levels d = 10, 9: software-pipelined
__global__ void __launch_bounds__(NT, 1)
level_mma(int d, const int* __restrict__ x_idx, const float* __restrict__ bt,
          int pin, int pout) {
    extern __shared__ char smem[];
    uint32_t sb = smem_u32(smem);
    const int tid = threadIdx.x;
    const int lane = tid & 31, wid = tid >> 5;
    const int wm = wid >> 3, wn = wid & 7;
    const int jp = wn * 4 + (lane & 3);
    __half2 bb2[5];
    load_common(smem, bt, bb2, jp);
    const __half* hc = g_h[pin];
    const __half* cc = g_c[pin];
    __half* ho = g_h[pout];
    __half* co = g_c[pout];
    const int n = 1 << d;          // 128-row tiles
    const int step = gridDim.x;
    int t = blockIdx.x;
    int p = 0, sq = 0;

    if (t < n)
        fill_a(smem, 0, hc + (size_t)(t << 7) * 128,
               x_idx + ((t << 7) >> d) * NTREE + (n - 1) + ((t << 7) & (n - 1)), 0, 128);
    __syncthreads();
    uint32_t accC[4][5][2] = {};
    if (t < n) {
        do_mma(smem, sb, accC, 128, wm, wn, lane);
        int nt = t + step;
        if (nt < n)
            fill_a(smem, 32768, hc + (size_t)(nt << 7) * 128,
                   x_idx + ((nt << 7) >> d) * NTREE + (n - 1) + ((nt << 7) & (n - 1)), 1, 128);
    }
    __syncthreads();

    for (; t < n; t += step) {
        int m0 = t << 7;
        int nt = t + step, nnt = nt + step;
        uint32_t accN[4][5][2] = {};
        if (nt < n)
            do_mma(smem, sb + (p ^ 1) * 32768, accN, 128, wm, wn, lane);
        epilogue_h(smem, sq, accC, 128, cc + (size_t)m0 * 128,
                   ho + (size_t)m0 * 64, co + (size_t)m0 * 64, bb2, wm, jp, lane);
        if (nnt < n)
            fill_a(smem, p * 32768, hc + (size_t)(nnt << 7) * 128,
                   x_idx + ((nnt << 7) >> d) * NTREE + (n - 1) + ((nnt << 7) & (n - 1)),
                   (sq + 2) % 3, 128);
        __syncthreads();
#pragma unroll
        for (int a = 0; a < 4; ++a)
#pragma unroll
            for (int g = 0; g < 5; ++g) {
                accC[a][g][0] = accN[a][g][0];
                accC[a][g][1] = accN[a][g][1];
            }
        p ^= 1;
        sq = (sq + 1) % 3;
    }
}

// ---------------- fused top levels d = 8..0, one CTA per batch
__global__ void __launch_bounds__(NT, 1)
top_mma(const int* __restrict__ x_idx, const float* __restrict__ bt) {
    extern __shared__ char smem[];
    uint32_t sb = smem_u32(smem);
    const int tid = threadIdx.x;
    const int lane = tid & 31, wid = tid >> 5;
    const int wm = wid >> 3, wn = wid & 7;
    const int jp = wn * 4 + (lane & 3);
    __half2 bb2[5];
    load_common(smem, bt, bb2, jp);
    __syncthreads();
    const int b = blockIdx.x;
    for (int d = 8; d >= 0; --d) {
        int n = 1 << d;
        int pin = (d + 1) & 1, pout = d & 1;
        int ntile = (n + 127) >> 7;
        for (int tt = 0; tt < ntile; ++tt) {
            int m0l = tt << 7;
            int count = n - m0l < 128 ? n - m0l : 128;
            fill_a(smem, 0, g_h[pin] + (size_t)(b * 2 * n + 2 * m0l) * 64,
                   x_idx + b * NTREE + (n - 1) + m0l, 0, count);
            __syncthreads();
            uint32_t acc[4][5][2] = {};
            do_mma(smem, sb, acc, count, wm, wn, lane);
            epilogue_h(smem, 0, acc, count,
                       g_c[pin] + (size_t)(b * 2 * n + 2 * m0l) * 64,
                       g_h[pout] + (size_t)(b * n + m0l) * 64,
                       g_c[pout] + (size_t)(b * n + m0l) * 64, bb2, wm, jp, lane);
            __syncthreads();
        }
    }
}

// ---------------- head
__global__ void head_kernel(const float* __restrict__ W1, const float* __restrict__ b1,
                            const float* __restrict__ W2, const float* __restrict__ b2,
                            const float* __restrict__ W_ih, const float* __restrict__ b_lstm,
                            const float* __restrict__ actorW, const float* __restrict__ actorb,
                            const float* __restrict__ vm, float* __restrict__ out) {
    __shared__ float sh[64], sf1[64], sfeat[128], slog[20], sinv[1];
    int b = blockIdx.x;
    int t = threadIdx.x;
    sh[t] = __half2float(g_h[0][b * 64 + t]);
    __syncthreads();
    float a = 0.f;
    for (int k = 0; k < 64; ++k) a += sh[k] * W1[k * 64 + t];
    a += b1[t];
    sf1[t] = fmaxf(a, 0.f);
    __syncthreads();
    float f = 0.f;
    for (int k = 0; k < 64; ++k) f += sf1[k] * W2[k * 64 + t];
    f += b2[t];
    sfeat[t] = f;
    __syncthreads();
    float gi = 0.f, gg = 0.f, go = 0.f;
    for (int k = 0; k < 64; ++k) {
        float fk = sfeat[k];
        gi += fk * W_ih[k * 256 + t];
        gg += fk * W_ih[k * 256 + 128 + t];
        go += fk * W_ih[k * 256 + 192 + t];
    }
    gi += b_lstm[t];
    gg += b_lstm[128 + t];
    go += b_lstm[192 + t];
    float cg = (1.f / (1.f + expf(-gi))) * tanhf(gg);
    float hg = (1.f / (1.f + expf(-go))) * tanhf(cg);
    sfeat[64 + t] = hg;
    __syncthreads();
    if (t < 20) {
        float l = 0.f;
        for (int dd = 0; dd < 128; ++dd) l += sfeat[dd] * actorW[dd * 20 + t];
        l = logf(vm[t]) + l * vm[t] + actorb[t] * vm[t];
        slog[t] = l / 3.0f;
    }
    __syncthreads();
    if (t == 0) {
        float mx = slog[0];
        for (int k = 1; k < 20; ++k) mx = fmaxf(mx, slog[k]);
        float s = 0.f;
        for (int k = 0; k < 20; ++k) {
            float e = expf(slog[k] - mx);
            slog[k] = e;
            s += e;
        }
        sinv[0] = 1.f / s;
    }
    __syncthreads();
    if (t < 20) out[b * 20 + t] = slog[t] * sinv[0];
}

extern "C" void kernel_launch(void* const* d_in, const int* in_sizes, int n_in,
                              void* d_out, int out_size) {
    const int*   x_idx  = (const int*)d_in[0];
    const float* vm     = (const float*)d_in[1];
    const float* Wx     = (const float*)d_in[2];
    const float* Ua     = (const float*)d_in[3];
    const float* Ub     = (const float*)d_in[4];
    const float* bt     = (const float*)d_in[5];
    const float* W_ih   = (const float*)d_in[6];
    const float* b_lstm = (const float*)d_in[8];
    const float* W1     = (const float*)d_in[9];
    const float* b1     = (const float*)d_in[10];
    const float* W2     = (const float*)d_in[11];
    const float* b2     = (const float*)d_in[12];
    const float* actorW = (const float*)d_in[13];
    const float* actorb = (const float*)d_in[14];
    float* out = (float*)d_out;

    cudaFuncSetAttribute(level_mma, cudaFuncAttributeMaxDynamicSharedMemorySize, SMEM_TOTAL);
    cudaFuncSetAttribute(top_mma, cudaFuncAttributeMaxDynamicSharedMemorySize, SMEM_TOTAL);

    prep_kernel<<<80, 256>>>(Ua, Ub, Wx);
    leaf_kernel<<<(BSZ * 2048 * 16) / 256, 256>>>(x_idx, bt);

    for (int d = 10; d >= 9; --d) {
        int ntile = 1 << d;
        int grid = ntile < 152 ? ntile : 152;
        level_mma<<<grid, NT, SMEM_TOTAL>>>(d, x_idx, bt, (d + 1) & 1, d & 1);
    }
    top_mma<<<BSZ, NT, SMEM_TOTAL>>>(x_idx, bt);

    head_kernel<<<BSZ, 64>>>(W1, b1, W2, b2, W_ih, b_lstm, actorW, actorb, vm, out);
}

// round 9
// speedup vs baseline: 1.2247x; 1.1772x over previous
#include <cuda_runtime.h>
#include <cuda_fp16.h>
#include <math.h>
#include <cstdint>

#define BSZ 128
#define NTREE 4095
#define NT 512

// smem layout (bytes):
//   buffer p (p=0,1) at p*67584:  A tile 32KB @ +0,  c-buf 34816B @ +32768 (stride 272)
//   B frags 80KB @ 135168;  idx slots @ 217088 (4 x 512B)
#define BUF_SZ 67584
#define CB_OFF 32768
#define CSTRIDE 272
#define B_OFF 135168
#define IDX_OFF 217088
#define SMEM_TOTAL 219136

__device__ __half g_h[2][(size_t)BSZ * 2048 * 64];
__device__ __half g_c[2][(size_t)BSZ * 2048 * 64];
__device__ uint32_t g_Bfrag[20480];   // f16x2 fragment-ordered U
__device__ uint32_t g_Wxb[20480];     // f16x2 Wx table [idx][g][colpair]

__device__ __forceinline__ uint32_t smem_u32(const void* p) {
    uint32_t a;
    asm("{ .reg .u64 t; cvta.to.shared.u64 t, %1; cvt.u32.u64 %0, t; }" : "=r"(a) : "l"(p));
    return a;
}
__device__ __forceinline__ __half2 tanh2(__half2 x) {
    uint32_t r, xi = *(uint32_t*)&x;
    asm("tanh.approx.f16x2 %0, %1;" : "=r"(r) : "r"(xi));
    return *(__half2*)&r;
}
__device__ __forceinline__ __half2 sig2(__half2 x) {
    const __half2 h = __float2half2_rn(0.5f);
    return __hfma2(tanh2(__hmul2(x, h)), h, h);
}
__device__ __forceinline__ void mma_f16(uint32_t d[2], uint32_t a0, uint32_t a1,
                                        uint32_t a2, uint32_t a3,
                                        uint32_t b0, uint32_t b1) {
    asm volatile(
        "mma.sync.aligned.m16n8k16.row.col.f16.f16.f16.f16 "
        "{%0,%1}, {%2,%3,%4,%5}, {%6,%7}, {%0,%1};"
        : "+r"(d[0]), "+r"(d[1])
        : "r"(a0), "r"(a1), "r"(a2), "r"(a3), "r"(b0), "r"(b1));
}

// ---------------- prep: U fragments + Wx f16 table
__global__ void prep_kernel(const float* __restrict__ Ua, const float* __restrict__ Ub,
                            const float* __restrict__ Wx) {
    int id = blockIdx.x * blockDim.x + threadIdx.x;   // 20480
    if (id >= 20480) return;
    {   // U: [g][wn][ks][lane][j]
        int j = id & 1;
        int lane = (id >> 1) & 31;
        int ks = (id >> 6) & 7;
        int wn = (id >> 9) & 7;
        int g = id >> 12;
        int k0 = ks * 16 + (lane & 3) * 2 + j * 8;
        int n = g * 64 + wn * 8 + (lane >> 2);
        float v0 = (k0 < 64) ? Ua[k0 * 320 + n] : Ub[(k0 - 64) * 320 + n];
        float v1 = (k0 + 1 < 64) ? Ua[(k0 + 1) * 320 + n] : Ub[(k0 + 1 - 64) * 320 + n];
        __half2 p = __floats2half2_rn(v0, v1);
        g_Bfrag[id] = *(uint32_t*)&p;
    }
    {   // Wx: [idx][g][jp] = cols (g*64+2jp, +1)
        int idx = id / 160;
        int rem = id - idx * 160;
        int g = rem >> 5, jp = rem & 31;
        const float* w = Wx + idx * 320 + g * 64 + 2 * jp;
        __half2 p = __floats2half2_rn(w[0], w[1]);
        g_Wxb[id] = *(uint32_t*)&p;
    }
}

// ---------------- common tile pieces
__device__ __forceinline__ void fill_a(char* smem, int abase,
                                       const __half* __restrict__ asrc,
                                       const int* __restrict__ idxp, int islot,
                                       int nvalid) {
    int tid = threadIdx.x;
    const uint4* src = (const uint4*)asrc;
#pragma unroll
    for (int i = 0; i < 4; ++i) {
        int f = tid + i * NT;
        int row = f >> 4, c = f & 15;
        uint4 v = make_uint4(0, 0, 0, 0);
        if (row < nvalid) v = src[f];
        *(uint4*)(smem + abase + row * 256 + ((c ^ (row & 7)) << 4)) = v;
    }
    if (tid < 128)
        *(int*)(smem + IDX_OFF + islot * 512 + tid * 4) = (tid < nvalid) ? idxp[tid] : 0;
}

// fused d10 fill: compute leaf children h,c from Wx table, h -> A (swizzled), c -> cbuf
__device__ __forceinline__ void fill_children(char* smem, int bufbase,
                                              const int* __restrict__ cidx,
                                              const int* __restrict__ pidx, int islot,
                                              const __half2 bbl[3]) {
    int tid = threadIdx.x;
    int lane = tid & 31, w = tid >> 5;
    const __half2* wxt = (const __half2*)g_Wxb;
#pragma unroll
    for (int it = 0; it < 16; ++it) {
        int child = w + it * 16;              // 0..255, warp-uniform
        int idx = cidx[child];
        const __half2* wr = wxt + idx * 160;
        __half2 zi = __hadd2(wr[lane], bbl[0]);
        __half2 zo = __hadd2(wr[96 + lane], bbl[1]);
        __half2 zu = __hadd2(wr[128 + lane], bbl[2]);
        __half2 c2 = __hmul2(sig2(zi), tanh2(zu));
        __half2 h2 = __hmul2(sig2(zo), tanh2(c2));
        int row = child >> 1, side = child & 1;
        int chunk = side * 8 + (lane >> 2);
        int aaddr = bufbase + row * 256 + ((chunk ^ (row & 7)) << 4) + (lane & 3) * 4;
        *(uint32_t*)(smem + aaddr) = *(uint32_t*)&h2;
        *(uint32_t*)(smem + bufbase + CB_OFF + row * CSTRIDE + side * 128 + lane * 4) =
            *(uint32_t*)&c2;
    }
    if (tid < 128)
        *(int*)(smem + IDX_OFF + islot * 512 + tid * 4) = pidx[tid];
}

__device__ __forceinline__ void do_mma(char* smem, uint32_t sA, uint32_t acc[4][5][2],
                                       int nvalid, int wm, int wn, int lane) {
    const int row_local = (lane & 7) | (((lane >> 3) & 1) << 3);
    const int hi = (lane >> 4) & 1;
#pragma unroll
    for (int ks = 0; ks < 8; ++ks) {
        uint2 bf[5];
#pragma unroll
        for (int g = 0; g < 5; ++g)
            bf[g] = *(const uint2*)(smem + B_OFF + ((((g * 8 + wn) * 8 + ks) * 32 + lane) << 3));
        int c = ks * 2 + hi;
#pragma unroll
        for (int mfl = 0; mfl < 4; ++mfl) {
            int mf = wm * 4 + mfl;
            if (mf * 16 < nvalid) {
                uint32_t addr = sA + (mf * 16 + row_local) * 256 + ((c ^ (lane & 7)) << 4);
                uint32_t a0, a1, a2, a3;
                asm volatile("ldmatrix.sync.aligned.m8n8.x4.shared.b16 {%0,%1,%2,%3}, [%4];"
                             : "=r"(a0), "=r"(a1), "=r"(a2), "=r"(a3) : "r"(addr));
#pragma unroll
                for (int g = 0; g < 5; ++g)
                    mma_f16(acc[mfl][g], a0, a1, a2, a3, bf[g].x, bf[g].y);
            }
        }
    }
}

// gate math for one (row, colpair) given z accs + Wx + bias + child c
__device__ __forceinline__ void gates(const __half2 z[5], __half2 ca, __half2 cb,
                                      __half2& hn, __half2& cn) {
    cn = __hfma2(sig2(z[1]), ca,
          __hfma2(sig2(z[2]), cb,
           __hmul2(sig2(z[0]), tanh2(z[4]))));
    hn = __hmul2(sig2(z[3]), tanh2(cn));
}

// epilogue variant A: child c from gmem (d9 / top levels)
__device__ __forceinline__ void epilogue_h(char* smem, int islot, uint32_t acc[4][5][2],
                                           int nvalid,
                                           const __half* __restrict__ csrc,
                                           __half* __restrict__ houtp,
                                           __half* __restrict__ coutp,
                                           const __half2 bb2[5], int wm, int jp, int lane) {
#pragma unroll
    for (int mfl = 0; mfl < 4; ++mfl) {
#pragma unroll
        for (int half = 0; half < 2; ++half) {
            int rloc = wm * 64 + mfl * 16 + half * 8 + (lane >> 2);
            if (rloc < nvalid) {
                int idx = *(const int*)(smem + IDX_OFF + islot * 512 + rloc * 4);
                const __half2* w = (const __half2*)g_Wxb + idx * 160 + jp;
                __half2 z[5];
#pragma unroll
                for (int g = 0; g < 5; ++g)
                    z[g] = __hadd2(__hadd2(*(__half2*)&acc[mfl][g][half], w[g * 32]), bb2[g]);
                __half2 ca = *(const __half2*)(csrc + (size_t)rloc * 128 + 2 * jp);
                __half2 cb = *(const __half2*)(csrc + (size_t)rloc * 128 + 64 + 2 * jp);
                __half2 hn, cn;
                gates(z, ca, cb, hn, cn);
                *(uint32_t*)(houtp + (size_t)rloc * 64 + 2 * jp) = *(uint32_t*)&hn;
                *(uint32_t*)(coutp + (size_t)rloc * 64 + 2 * jp) = *(uint32_t*)&cn;
            }
        }
    }
}

// epilogue variant B: child c from smem cbuf (fused d10)
__device__ __forceinline__ void epilogue_f(char* smem, int bufbase, int islot,
                                           uint32_t acc[4][5][2],
                                           __half* __restrict__ houtp,
                                           __half* __restrict__ coutp,
                                           const __half2 bb2[5], int wm, int jp, int lane) {
#pragma unroll
    for (int mfl = 0; mfl < 4; ++mfl) {
#pragma unroll
        for (int half = 0; half < 2; ++half) {
            int rloc = wm * 64 + mfl * 16 + half * 8 + (lane >> 2);
            int idx = *(const int*)(smem + IDX_OFF + islot * 512 + rloc * 4);
            const __half2* w = (const __half2*)g_Wxb + idx * 160 + jp;
            __half2 z[5];
#pragma unroll
            for (int g = 0; g < 5; ++g)
                z[g] = __hadd2(__hadd2(*(__half2*)&acc[mfl][g][half], w[g * 32]), bb2[g]);
            __half2 ca = *(const __half2*)(smem + bufbase + CB_OFF + rloc * CSTRIDE + jp * 4);
            __half2 cb = *(const __half2*)(smem + bufbase + CB_OFF + rloc * CSTRIDE + 128 + jp * 4);
            __half2 hn, cn;
            gates(z, ca, cb, hn, cn);
            *(uint32_t*)(houtp + (size_t)rloc * 64 + 2 * jp) = *(uint32_t*)&hn;
            *(uint32_t*)(coutp + (size_t)rloc * 64 + 2 * jp) = *(uint32_t*)&cn;
        }
    }
}

__device__ __forceinline__ void load_common(char* smem, const float* bt, __half2 bb2[5],
                                            __half2 bbl[3], int jp) {
    int tid = threadIdx.x;
    const uint4* src = (const uint4*)g_Bfrag;
    uint4* dst = (uint4*)(smem + B_OFF);
#pragma unroll
    for (int i = 0; i < 10; ++i) dst[tid + i * NT] = src[tid + i * NT];
#pragma unroll
    for (int g = 0; g < 5; ++g) {
        float2 bv = *(const float2*)(bt + g * 64 + 2 * jp);
        bb2[g] = __floats2half2_rn(bv.x, bv.y);
    }
    int lane = tid & 31;
    const int gsel[3] = {0, 3, 4};
#pragma unroll
    for (int e = 0; e < 3; ++e) {
        float2 bv = *(const float2*)(bt + gsel[e] * 64 + 2 * lane);
        bbl[e] = __floats2half2_rn(bv.x, bv.y);
    }
}

// ---------------- fused leaf + level d=10: children computed in-tile
__global__ void __launch_bounds__(NT, 1)
level10_fused(const int* __restrict__ x_idx, const float* __restrict__ bt) {
    extern __shared__ char smem[];
    uint32_t sb = smem_u32(smem);
    const int tid = threadIdx.x;
    const int lane = tid & 31, wid = tid >> 5;
    const int wm = wid >> 3, wn = wid & 7;
    const int jp = wn * 4 + (lane & 3);
    __half2 bb2[5], bbl[3];
    load_common(smem, bt, bb2, bbl, jp);
    __half* ho = g_h[0];
    __half* co = g_c[0];
    const int n = 1024;
    int t = blockIdx.x;
    int p = 0;
    if (t < n) {
        int m0 = t << 7, b = m0 >> 10, jl0 = m0 & 1023;
        fill_children(smem, 0, x_idx + b * NTREE + 2047 + 2 * jl0,
                      x_idx + b * NTREE + 1023 + jl0, 0, bbl);
    }
    __syncthreads();
    for (; t < n; t += gridDim.x) {
        int m0 = t << 7;
        uint32_t acc[4][5][2] = {};
        do_mma(smem, sb + p * BUF_SZ, acc, 128, wm, wn, lane);
        epilogue_f(smem, p * BUF_SZ, p, acc, ho + (size_t)m0 * 64, co + (size_t)m0 * 64,
                   bb2, wm, jp, lane);
        int nt = t + gridDim.x;
        if (nt < n) {
            int m1 = nt << 7, b1 = m1 >> 10, jl1 = m1 & 1023;
            fill_children(smem, (p ^ 1) * BUF_SZ, x_idx + b1 * NTREE + 2047 + 2 * jl1,
                          x_idx + b1 * NTREE + 1023 + jl1, p ^ 1, bbl);
        }
        __syncthreads();
        p ^= 1;
    }
}

// ---------------- level d = 9 (round-8 pipelined form)
__global__ void __launch_bounds__(NT, 1)
level_mma(int d, const int* __restrict__ x_idx, const float* __restrict__ bt,
          int pin, int pout) {
    extern __shared__ char smem[];
    uint32_t sb = smem_u32(smem);
    const int tid = threadIdx.x;
    const int lane = tid & 31, wid = tid >> 5;
    const int wm = wid >> 3, wn = wid & 7;
    const int jp = wn * 4 + (lane & 3);
    __half2 bb2[5], bbl[3];
    load_common(smem, bt, bb2, bbl, jp);
    const __half* hc = g_h[pin];
    const __half* cc = g_c[pin];
    __half* ho = g_h[pout];
    __half* co = g_c[pout];
    const int n = 1 << d;
    const int step = gridDim.x;
    int t = blockIdx.x;
    int p = 0, sq = 0;

    if (t < n)
        fill_a(smem, 0, hc + (size_t)(t << 7) * 128,
               x_idx + ((t << 7) >> d) * NTREE + (n - 1) + ((t << 7) & (n - 1)), 0, 128);
    __syncthreads();
    uint32_t accC[4][5][2] = {};
    if (t < n) {
        do_mma(smem, sb, accC, 128, wm, wn, lane);
        int nt = t + step;
        if (nt < n)
            fill_a(smem, BUF_SZ, hc + (size_t)(nt << 7) * 128,
                   x_idx + ((nt << 7) >> d) * NTREE + (n - 1) + ((nt << 7) & (n - 1)), 1, 128);
    }
    __syncthreads();

    for (; t < n; t += step) {
        int m0 = t << 7;
        int nt = t + step, nnt = nt + step;
        uint32_t accN[4][5][2] = {};
        if (nt < n)
            do_mma(smem, sb + (p ^ 1) * BUF_SZ, accN, 128, wm, wn, lane);
        epilogue_h(smem, sq, accC, 128, cc + (size_t)m0 * 128,
                   ho + (size_t)m0 * 64, co + (size_t)m0 * 64, bb2, wm, jp, lane);
        if (nnt < n)
            fill_a(smem, p * BUF_SZ, hc + (size_t)(nnt << 7) * 128,
                   x_idx + ((nnt << 7) >> d) * NTREE + (n - 1) + ((nnt << 7) & (n - 1)),
                   (sq + 2) & 3, 128);
        __syncthreads();
#pragma unroll
        for (int a = 0; a < 4; ++a)
#pragma unroll
            for (int g = 0; g < 5; ++g) {
                accC[a][g][0] = accN[a][g][0];
                accC[a][g][1] = accN[a][g][1];
            }
        p ^= 1;
        sq = (sq + 1) & 3;
    }
}

// ---------------- fused top levels d = 8..0 + head, one CTA per batch
__global__ void __launch_bounds__(NT, 1)
top_mma(const int* __restrict__ x_idx, const float* __restrict__ bt,
        const float* __restrict__ W1, const float* __restrict__ b1,
        const float* __restrict__ W2, const float* __restrict__ b2,
        const float* __restrict__ W_ih, const float* __restrict__ b_lstm,
        const float* __restrict__ actorW, const float* __restrict__ actorb,
        const float* __restrict__ vm, float* __restrict__ out) {
    extern __shared__ char smem[];
    uint32_t sb = smem_u32(smem);
    const int tid = threadIdx.x;
    const int lane = tid & 31, wid = tid >> 5;
    const int wm = wid >> 3, wn = wid & 7;
    const int jp = wn * 4 + (lane & 3);
    __half2 bb2[5], bbl[3];
    load_common(smem, bt, bb2, bbl, jp);
    __syncthreads();
    const int b = blockIdx.x;
    for (int d = 8; d >= 0; --d) {
        int n = 1 << d;
        int pin = (d + 1) & 1, pout = d & 1;
        int ntile = (n + 127) >> 7;
        for (int tt = 0; tt < ntile; ++tt) {
            int m0l = tt << 7;
            int count = n - m0l < 128 ? n - m0l : 128;
            fill_a(smem, 0, g_h[pin] + (size_t)(b * 2 * n + 2 * m0l) * 64,
                   x_idx + b * NTREE + (n - 1) + m0l, 0, count);
            __syncthreads();
            uint32_t acc[4][5][2] = {};
            do_mma(smem, sb, acc, count, wm, wn, lane);
            epilogue_h(smem, 0, acc, count,
                       g_c[pin] + (size_t)(b * 2 * n + 2 * m0l) * 64,
                       g_h[pout] + (size_t)(b * n + m0l) * 64,
                       g_c[pout] + (size_t)(b * n + m0l) * 64, bb2, wm, jp, lane);
            __syncthreads();
        }
    }
    // ---- head phase (threads 0..63 compute; all threads hit barriers)
    float* sh = (float*)smem;          // [64]
    float* sf1 = sh + 64;              // [64]
    float* sfeat = sf1 + 64;           // [128]
    float* slog = sfeat + 128;         // [20]
    float* sinv = slog + 20;           // [1]
    int t = tid;
    if (t < 64) sh[t] = __half2float(g_h[0][b * 64 + t]);
    __syncthreads();
    if (t < 64) {
        float a = 0.f;
        for (int k = 0; k < 64; ++k) a += sh[k] * W1[k * 64 + t];
        sf1[t] = fmaxf(a + b1[t], 0.f);
    }
    __syncthreads();
    if (t < 64) {
        float f = 0.f;
        for (int k = 0; k < 64; ++k) f += sf1[k] * W2[k * 64 + t];
        sfeat[t] = f + b2[t];
    }
    __syncthreads();
    if (t < 64) {
        float gi = 0.f, gg = 0.f, go = 0.f;
        for (int k = 0; k < 64; ++k) {
            float fk = sfeat[k];
            gi += fk * W_ih[k * 256 + t];
            gg += fk * W_ih[k * 256 + 128 + t];
            go += fk * W_ih[k * 256 + 192 + t];
        }
        gi += b_lstm[t];
        gg += b_lstm[128 + t];
        go += b_lstm[192 + t];
        float cg = (1.f / (1.f + expf(-gi))) * tanhf(gg);
        sfeat[64 + t] = (1.f / (1.f + expf(-go))) * tanhf(cg);
    }
    __syncthreads();
    if (t < 20) {
        float l = 0.f;
        for (int dd = 0; dd < 128; ++dd) l += sfeat[dd] * actorW[dd * 20 + t];
        l = logf(vm[t]) + l * vm[t] + actorb[t] * vm[t];
        slog[t] = l / 3.0f;
    }
    __syncthreads();
    if (t == 0) {
        float mx = slog[0];
        for (int k = 1; k < 20; ++k) mx = fmaxf(mx, slog[k]);
        float s = 0.f;
        for (int k = 0; k < 20; ++k) {
            float e = expf(slog[k] - mx);
            slog[k] = e;
            s += e;
        }
        sinv[0] = 1.f / s;
    }
    __syncthreads();
    if (t < 20) out[b * 20 + t] = slog[t] * sinv[0];
}

extern "C" void kernel_launch(void* const* d_in, const int* in_sizes, int n_in,
                              void* d_out, int out_size) {
    const int*   x_idx  = (const int*)d_in[0];
    const float* vm     = (const float*)d_in[1];
    const float* Wx     = (const float*)d_in[2];
    const float* Ua     = (const float*)d_in[3];
    const float* Ub     = (const float*)d_in[4];
    const float* bt     = (const float*)d_in[5];
    const float* W_ih   = (const float*)d_in[6];
    const float* b_lstm = (const float*)d_in[8];
    const float* W1     = (const float*)d_in[9];
    const float* b1     = (const float*)d_in[10];
    const float* W2     = (const float*)d_in[11];
    const float* b2     = (const float*)d_in[12];
    const float* actorW = (const float*)d_in[13];
    const float* actorb = (const float*)d_in[14];
    float* out = (float*)d_out;

    cudaFuncSetAttribute(level10_fused, cudaFuncAttributeMaxDynamicSharedMemorySize, SMEM_TOTAL);
    cudaFuncSetAttribute(level_mma, cudaFuncAttributeMaxDynamicSharedMemorySize, SMEM_TOTAL);
    cudaFuncSetAttribute(top_mma, cudaFuncAttributeMaxDynamicSharedMemorySize, SMEM_TOTAL);

    prep_kernel<<<80, 256>>>(Ua, Ub, Wx);
    level10_fused<<<152, NT, SMEM_TOTAL>>>(x_idx, bt);
    level_mma<<<152, NT, SMEM_TOTAL>>>(9, x_idx, bt, 0, 1);
    top_mma<<<BSZ, NT, SMEM_TOTAL>>>(x_idx, bt, W1, b1, W2, b2, W_ih, b_lstm,
                                     actorW, actorb, vm, out);
}

// round 10
// speedup vs baseline: 1.4372x; 1.1735x over previous
#include <cuda_runtime.h>
#include <cuda_fp16.h>
#include <math.h>
#include <cstdint>

#define BSZ 128
#define NTREE 4095
#define NT 512

// smem layout (bytes):
//   buffer p (p=0,1) at p*67584:  A tile 32KB @ +0,  c-buf 34816B @ +32768 (stride 272)
//   B frags 80KB @ 135168;  idx region @ 217088 (2KB)
#define BUF_SZ 67584
#define CB_OFF 32768
#define CSTRIDE 272
#define B_OFF 135168
#define IDX_OFF 217088
#define SMEM_TOTAL 219136

__device__ __half g_h[2][(size_t)BSZ * 2048 * 64];
__device__ __half g_c[2][(size_t)BSZ * 2048 * 64];
__device__ uint32_t g_Bfrag[20480];   // f16x2 fragment-ordered U
__device__ uint32_t g_Wxb[20480];     // f16x2 Wx table [idx][g][colpair]

__device__ __forceinline__ uint32_t smem_u32(const void* p) {
    uint32_t a;
    asm("{ .reg .u64 t; cvta.to.shared.u64 t, %1; cvt.u32.u64 %0, t; }" : "=r"(a) : "l"(p));
    return a;
}
__device__ __forceinline__ __half2 tanh2(__half2 x) {
    uint32_t r, xi = *(uint32_t*)&x;
    asm("tanh.approx.f16x2 %0, %1;" : "=r"(r) : "r"(xi));
    return *(__half2*)&r;
}
__device__ __forceinline__ __half2 sig2(__half2 x) {
    const __half2 h = __float2half2_rn(0.5f);
    return __hfma2(tanh2(__hmul2(x, h)), h, h);
}
__device__ __forceinline__ void mma_f16(uint32_t d[2], uint32_t a0, uint32_t a1,
                                        uint32_t a2, uint32_t a3,
                                        uint32_t b0, uint32_t b1) {
    asm volatile(
        "mma.sync.aligned.m16n8k16.row.col.f16.f16.f16.f16 "
        "{%0,%1}, {%2,%3,%4,%5}, {%6,%7}, {%0,%1};"
        : "+r"(d[0]), "+r"(d[1])
        : "r"(a0), "r"(a1), "r"(a2), "r"(a3), "r"(b0), "r"(b1));
}

// ---------------- prep: U fragments + Wx f16 table
__global__ void prep_kernel(const float* __restrict__ Ua, const float* __restrict__ Ub,
                            const float* __restrict__ Wx) {
    int id = blockIdx.x * blockDim.x + threadIdx.x;   // 20480
    if (id >= 20480) return;
    {   // U: [g][wn][ks][lane][j]
        int j = id & 1;
        int lane = (id >> 1) & 31;
        int ks = (id >> 6) & 7;
        int wn = (id >> 9) & 7;
        int g = id >> 12;
        int k0 = ks * 16 + (lane & 3) * 2 + j * 8;
        int n = g * 64 + wn * 8 + (lane >> 2);
        float v0 = (k0 < 64) ? Ua[k0 * 320 + n] : Ub[(k0 - 64) * 320 + n];
        float v1 = (k0 + 1 < 64) ? Ua[(k0 + 1) * 320 + n] : Ub[(k0 + 1 - 64) * 320 + n];
        __half2 p = __floats2half2_rn(v0, v1);
        g_Bfrag[id] = *(uint32_t*)&p;
    }
    {   // Wx: [idx][g][jp] = cols (g*64+2jp, +1)
        int idx = id / 160;
        int rem = id - idx * 160;
        int g = rem >> 5, jp = rem & 31;
        const float* w = Wx + idx * 320 + g * 64 + 2 * jp;
        __half2 p = __floats2half2_rn(w[0], w[1]);
        g_Wxb[id] = *(uint32_t*)&p;
    }
}

// ---------------- common tile pieces
__device__ __forceinline__ void fill_a(char* smem, int abase,
                                       const __half* __restrict__ asrc,
                                       const int* __restrict__ idxp, int islot,
                                       int nvalid) {
    int tid = threadIdx.x;
    const uint4* src = (const uint4*)asrc;
#pragma unroll
    for (int i = 0; i < 4; ++i) {
        int f = tid + i * NT;
        int row = f >> 4, c = f & 15;
        uint4 v = make_uint4(0, 0, 0, 0);
        if (row < nvalid) v = src[f];
        *(uint4*)(smem + abase + row * 256 + ((c ^ (row & 7)) << 4)) = v;
    }
    if (tid < 128)
        *(int*)(smem + IDX_OFF + islot * 512 + tid * 4) = (tid < nvalid) ? idxp[tid] : 0;
}

__device__ __forceinline__ void fill_a_noidx(char* smem, int abase,
                                             const __half* __restrict__ asrc) {
    int tid = threadIdx.x;
    const uint4* src = (const uint4*)asrc;
#pragma unroll
    for (int i = 0; i < 4; ++i) {
        int f = tid + i * NT;
        int row = f >> 4, c = f & 15;
        uint4 v = src[f];
        *(uint4*)(smem + abase + row * 256 + ((c ^ (row & 7)) << 4)) = v;
    }
}

// fused d10 fill: compute leaf children h,c from Wx table, h -> A (swizzled), c -> cbuf
__device__ __forceinline__ void fill_children(char* smem, int bufbase,
                                              const int* __restrict__ cidx,
                                              const int* __restrict__ pidx, int islot,
                                              const __half2 bbl[3]) {
    int tid = threadIdx.x;
    int lane = tid & 31, w = tid >> 5;
    const __half2* wxt = (const __half2*)g_Wxb;
#pragma unroll
    for (int it = 0; it < 16; ++it) {
        int child = w + it * 16;              // 0..255, warp-uniform
        int idx = cidx[child];
        const __half2* wr = wxt + idx * 160;
        __half2 zi = __hadd2(wr[lane], bbl[0]);
        __half2 zo = __hadd2(wr[96 + lane], bbl[1]);
        __half2 zu = __hadd2(wr[128 + lane], bbl[2]);
        __half2 c2 = __hmul2(sig2(zi), tanh2(zu));
        __half2 h2 = __hmul2(sig2(zo), tanh2(c2));
        int row = child >> 1, side = child & 1;
        int chunk = side * 8 + (lane >> 2);
        int aaddr = bufbase + row * 256 + ((chunk ^ (row & 7)) << 4) + (lane & 3) * 4;
        *(uint32_t*)(smem + aaddr) = *(uint32_t*)&h2;
        *(uint32_t*)(smem + bufbase + CB_OFF + row * CSTRIDE + side * 128 + lane * 4) =
            *(uint32_t*)&c2;
    }
    if (tid < 128)
        *(int*)(smem + IDX_OFF + islot * 512 + tid * 4) = pidx[tid];
}

__device__ __forceinline__ void do_mma(char* smem, uint32_t sA, uint32_t acc[4][5][2],
                                       int nvalid, int wm, int wn, int lane) {
    const int row_local = (lane & 7) | (((lane >> 3) & 1) << 3);
    const int hi = (lane >> 4) & 1;
#pragma unroll
    for (int ks = 0; ks < 8; ++ks) {
        uint2 bf[5];
#pragma unroll
        for (int g = 0; g < 5; ++g)
            bf[g] = *(const uint2*)(smem + B_OFF + ((((g * 8 + wn) * 8 + ks) * 32 + lane) << 3));
        int c = ks * 2 + hi;
#pragma unroll
        for (int mfl = 0; mfl < 4; ++mfl) {
            int mf = wm * 4 + mfl;
            if (mf * 16 < nvalid) {
                uint32_t addr = sA + (mf * 16 + row_local) * 256 + ((c ^ (lane & 7)) << 4);
                uint32_t a0, a1, a2, a3;
                asm volatile("ldmatrix.sync.aligned.m8n8.x4.shared.b16 {%0,%1,%2,%3}, [%4];"
                             : "=r"(a0), "=r"(a1), "=r"(a2), "=r"(a3) : "r"(addr));
#pragma unroll
                for (int g = 0; g < 5; ++g)
                    mma_f16(acc[mfl][g], a0, a1, a2, a3, bf[g].x, bf[g].y);
            }
        }
    }
}

// gate math for one (row, colpair)
__device__ __forceinline__ void gates(const __half2 z[5], __half2 ca, __half2 cb,
                                      __half2& hn, __half2& cn) {
    cn = __hfma2(sig2(z[1]), ca,
          __hfma2(sig2(z[2]), cb,
           __hmul2(sig2(z[0]), tanh2(z[4]))));
    hn = __hmul2(sig2(z[3]), tanh2(cn));
}

// epilogue A: child c from gmem, out to gmem (d9)
__device__ __forceinline__ void epilogue_h(char* smem, int islot, uint32_t acc[4][5][2],
                                           int nvalid,
                                           const __half* __restrict__ csrc,
                                           __half* __restrict__ houtp,
                                           __half* __restrict__ coutp,
                                           const __half2 bb2[5], int wm, int jp, int lane) {
#pragma unroll
    for (int mfl = 0; mfl < 4; ++mfl) {
#pragma unroll
        for (int half = 0; half < 2; ++half) {
            int rloc = wm * 64 + mfl * 16 + half * 8 + (lane >> 2);
            if (rloc < nvalid) {
                int idx = *(const int*)(smem + IDX_OFF + islot * 512 + rloc * 4);
                const __half2* w = (const __half2*)g_Wxb + idx * 160 + jp;
                __half2 z[5];
#pragma unroll
                for (int g = 0; g < 5; ++g)
                    z[g] = __hadd2(__hadd2(*(__half2*)&acc[mfl][g][half], w[g * 32]), bb2[g]);
                __half2 ca = *(const __half2*)(csrc + (size_t)rloc * 128 + 2 * jp);
                __half2 cb = *(const __half2*)(csrc + (size_t)rloc * 128 + 64 + 2 * jp);
                __half2 hn, cn;
                gates(z, ca, cb, hn, cn);
                *(uint32_t*)(houtp + (size_t)rloc * 64 + 2 * jp) = *(uint32_t*)&hn;
                *(uint32_t*)(coutp + (size_t)rloc * 64 + 2 * jp) = *(uint32_t*)&cn;
            }
        }
    }
}

// epilogue B: child c from smem cbuf (fused d10 layout), out to gmem
__device__ __forceinline__ void epilogue_f(char* smem, int bufbase, int islot,
                                           uint32_t acc[4][5][2],
                                           __half* __restrict__ houtp,
                                           __half* __restrict__ coutp,
                                           const __half2 bb2[5], int wm, int jp, int lane) {
#pragma unroll
    for (int mfl = 0; mfl < 4; ++mfl) {
#pragma unroll
        for (int half = 0; half < 2; ++half) {
            int rloc = wm * 64 + mfl * 16 + half * 8 + (lane >> 2);
            int idx = *(const int*)(smem + IDX_OFF + islot * 512 + rloc * 4);
            const __half2* w = (const __half2*)g_Wxb + idx * 160 + jp;
            __half2 z[5];
#pragma unroll
            for (int g = 0; g < 5; ++g)
                z[g] = __hadd2(__hadd2(*(__half2*)&acc[mfl][g][half], w[g * 32]), bb2[g]);
            __half2 ca = *(const __half2*)(smem + bufbase + CB_OFF + rloc * CSTRIDE + jp * 4);
            __half2 cb = *(const __half2*)(smem + bufbase + CB_OFF + rloc * CSTRIDE + 128 + jp * 4);
            __half2 hn, cn;
            gates(z, ca, cb, hn, cn);
            *(uint32_t*)(houtp + (size_t)rloc * 64 + 2 * jp) = *(uint32_t*)&hn;
            *(uint32_t*)(coutp + (size_t)rloc * 64 + 2 * jp) = *(uint32_t*)&cn;
        }
    }
}

// epilogue C (top): idx from preloaded smem; c from gmem (d8) or cbuf (interleaved
// layout row*272 + jp*8 + side*4); outputs written to the NEXT level's smem A tile
// (swizzled) + cbuf. No gmem output.
__device__ __forceinline__ void epi_top(char* smem, const int* __restrict__ sidx,
                                        uint32_t acc[4][5][2], int nvalid,
                                        const __half* __restrict__ csrc, int cbin,
                                        int outbase, int orow_off,
                                        const __half2 bb2[5], int wm, int jp, int lane) {
#pragma unroll
    for (int mfl = 0; mfl < 4; ++mfl) {
#pragma unroll
        for (int half = 0; half < 2; ++half) {
            int rloc = wm * 64 + mfl * 16 + half * 8 + (lane >> 2);
            if (rloc < nvalid) {
                int idx = sidx[rloc];
                const __half2* w = (const __half2*)g_Wxb + idx * 160 + jp;
                __half2 z[5];
#pragma unroll
                for (int g = 0; g < 5; ++g)
                    z[g] = __hadd2(__hadd2(*(__half2*)&acc[mfl][g][half], w[g * 32]), bb2[g]);
                __half2 ca, cb;
                if (csrc) {
                    ca = *(const __half2*)(csrc + (size_t)rloc * 128 + 2 * jp);
                    cb = *(const __half2*)(csrc + (size_t)rloc * 128 + 64 + 2 * jp);
                } else {
                    uint2 v = *(const uint2*)(smem + cbin + rloc * CSTRIDE + jp * 8);
                    ca = *(__half2*)&v.x;
                    cb = *(__half2*)&v.y;
                }
                __half2 hn, cn;
                gates(z, ca, cb, hn, cn);
                int orow = orow_off + (rloc >> 1);
                int side = rloc & 1;
                int chunk = (side * 8 + (jp >> 2)) ^ (orow & 7);
                *(uint32_t*)(smem + outbase + orow * 256 + (chunk << 4) + (jp & 3) * 4) =
                    *(uint32_t*)&hn;
                *(uint32_t*)(smem + outbase + CB_OFF + orow * CSTRIDE + jp * 8 + side * 4) =
                    *(uint32_t*)&cn;
            }
        }
    }
}

__device__ __forceinline__ void load_common(char* smem, const float* bt, __half2 bb2[5],
                                            __half2 bbl[3], int jp) {
    int tid = threadIdx.x;
    const uint4* src = (const uint4*)g_Bfrag;
    uint4* dst = (uint4*)(smem + B_OFF);
#pragma unroll
    for (int i = 0; i < 10; ++i) dst[tid + i * NT] = src[tid + i * NT];
#pragma unroll
    for (int g = 0; g < 5; ++g) {
        float2 bv = *(const float2*)(bt + g * 64 + 2 * jp);
        bb2[g] = __floats2half2_rn(bv.x, bv.y);
    }
    int lane = tid & 31;
    const int gsel[3] = {0, 3, 4};
#pragma unroll
    for (int e = 0; e < 3; ++e) {
        float2 bv = *(const float2*)(bt + gsel[e] * 64 + 2 * lane);
        bbl[e] = __floats2half2_rn(bv.x, bv.y);
    }
}

// ---------------- fused leaf + level d=10
__global__ void __launch_bounds__(NT, 1)
level10_fused(const int* __restrict__ x_idx, const float* __restrict__ bt) {
    extern __shared__ char smem[];
    uint32_t sb = smem_u32(smem);
    const int tid = threadIdx.x;
    const int lane = tid & 31, wid = tid >> 5;
    const int wm = wid >> 3, wn = wid & 7;
    const int jp = wn * 4 + (lane & 3);
    __half2 bb2[5], bbl[3];
    load_common(smem, bt, bb2, bbl, jp);
    __half* ho = g_h[0];
    __half* co = g_c[0];
    const int n = 1024;
    int t = blockIdx.x;
    int p = 0;
    if (t < n) {
        int m0 = t << 7, b = m0 >> 10, jl0 = m0 & 1023;
        fill_children(smem, 0, x_idx + b * NTREE + 2047 + 2 * jl0,
                      x_idx + b * NTREE + 1023 + jl0, 0, bbl);
    }
    __syncthreads();
    for (; t < n; t += gridDim.x) {
        int m0 = t << 7;
        uint32_t acc[4][5][2] = {};
        do_mma(smem, sb + p * BUF_SZ, acc, 128, wm, wn, lane);
        epilogue_f(smem, p * BUF_SZ, p, acc, ho + (size_t)m0 * 64, co + (size_t)m0 * 64,
                   bb2, wm, jp, lane);
        int nt = t + gridDim.x;
        if (nt < n) {
            int m1 = nt << 7, b1 = m1 >> 10, jl1 = m1 & 1023;
            fill_children(smem, (p ^ 1) * BUF_SZ, x_idx + b1 * NTREE + 2047 + 2 * jl1,
                          x_idx + b1 * NTREE + 1023 + jl1, p ^ 1, bbl);
        }
        __syncthreads();
        p ^= 1;
    }
}

// ---------------- level d = 9 (pipelined)
__global__ void __launch_bounds__(NT, 1)
level_mma(int d, const int* __restrict__ x_idx, const float* __restrict__ bt,
          int pin, int pout) {
    extern __shared__ char smem[];
    uint32_t sb = smem_u32(smem);
    const int tid = threadIdx.x;
    const int lane = tid & 31, wid = tid >> 5;
    const int wm = wid >> 3, wn = wid & 7;
    const int jp = wn * 4 + (lane & 3);
    __half2 bb2[5], bbl[3];
    load_common(smem, bt, bb2, bbl, jp);
    const __half* hc = g_h[pin];
    const __half* cc = g_c[pin];
    __half* ho = g_h[pout];
    __half* co = g_c[pout];
    const int n = 1 << d;
    const int step = gridDim.x;
    int t = blockIdx.x;
    int p = 0, sq = 0;

    if (t < n)
        fill_a(smem, 0, hc + (size_t)(t << 7) * 128,
               x_idx + ((t << 7) >> d) * NTREE + (n - 1) + ((t << 7) & (n - 1)), 0, 128);
    __syncthreads();
    uint32_t accC[4][5][2] = {};
    if (t < n) {
        do_mma(smem, sb, accC, 128, wm, wn, lane);
        int nt = t + step;
        if (nt < n)
            fill_a(smem, BUF_SZ, hc + (size_t)(nt << 7) * 128,
                   x_idx + ((nt << 7) >> d) * NTREE + (n - 1) + ((nt << 7) & (n - 1)), 1, 128);
    }
    __syncthreads();

    for (; t < n; t += step) {
        int m0 = t << 7;
        int nt = t + step, nnt = nt + step;
        uint32_t accN[4][5][2] = {};
        if (nt < n)
            do_mma(smem, sb + (p ^ 1) * BUF_SZ, accN, 128, wm, wn, lane);
        epilogue_h(smem, sq, accC, 128, cc + (size_t)m0 * 128,
                   ho + (size_t)m0 * 64, co + (size_t)m0 * 64, bb2, wm, jp, lane);
        if (nnt < n)
            fill_a(smem, p * BUF_SZ, hc + (size_t)(nnt << 7) * 128,
                   x_idx + ((nnt << 7) >> d) * NTREE + (n - 1) + ((nnt << 7) & (n - 1)),
                   (sq + 2) & 3, 128);
        __syncthreads();
#pragma unroll
        for (int a = 0; a < 4; ++a)
#pragma unroll
            for (int g = 0; g < 5; ++g) {
                accC[a][g][0] = accN[a][g][0];
                accC[a][g][1] = accN[a][g][1];
            }
        p ^= 1;
        sq = (sq + 1) & 3;
    }
}

// ---------------- fused top levels d = 8..0 + head, smem-resident chain
__global__ void __launch_bounds__(NT, 1)
top_mma(const int* __restrict__ x_idx, const float* __restrict__ bt,
        const float* __restrict__ W1, const float* __restrict__ b1,
        const float* __restrict__ W2, const float* __restrict__ b2,
        const float* __restrict__ W_ih, const float* __restrict__ b_lstm,
        const float* __restrict__ actorW, const float* __restrict__ actorb,
        const float* __restrict__ vm, float* __restrict__ out) {
    extern __shared__ char smem[];
    uint32_t sb = smem_u32(smem);
    const int tid = threadIdx.x;
    const int lane = tid & 31, wid = tid >> 5;
    const int wm = wid >> 3, wn = wid & 7;
    const int jp = wn * 4 + (lane & 3);
    __half2 bb2[5], bbl[3];
    load_common(smem, bt, bb2, bbl, jp);
    int* sidx = (int*)(smem + IDX_OFF);
    const int b = blockIdx.x;
    if (tid < 511) sidx[tid] = x_idx[b * NTREE + tid];

    // ---- d = 8: two 128-row tiles; A/c from gmem level-9 state; out -> smem buf1
    fill_a_noidx(smem, 0, g_h[1] + (size_t)b * 512 * 64);
    __syncthreads();
#pragma unroll
    for (int tt = 0; tt < 2; ++tt) {
        uint32_t acc[4][5][2] = {};
        do_mma(smem, sb, acc, 128, wm, wn, lane);
        __syncthreads();   // all mma reads of buf0 done before refill
        if (tt == 0)
            fill_a_noidx(smem, 0, g_h[1] + (size_t)(b * 512 + 256) * 64);
        epi_top(smem, sidx + 255 + tt * 128, acc, 128,
                g_c[1] + (size_t)(b * 512 + tt * 256) * 64,
                0, BUF_SZ, tt * 64, bb2, wm, jp, lane);
        __syncthreads();
    }

    // ---- levels 7..0, fully smem-resident, one barrier per level
    int p = 1;
#pragma unroll
    for (int d = 7; d >= 0; --d) {
        int n = 1 << d;
        uint32_t acc[4][5][2] = {};
        do_mma(smem, sb + p * BUF_SZ, acc, n, wm, wn, lane);
        epi_top(smem, sidx + (n - 1), acc, n, (const __half*)0,
                p * BUF_SZ + CB_OFF, (p ^ 1) * BUF_SZ, 0, bb2, wm, jp, lane);
        __syncthreads();
        p ^= 1;
    }
    // root h now in buf1 A row 0 (row 0 is swizzle-free -> contiguous 64 halves)

    // ---- head phase (threads 0..63 compute; all threads hit barriers)
    float* sh = (float*)smem;          // overlays buf0 (dead now)
    float* sf1 = sh + 64;
    float* sfeat = sf1 + 64;
    float* slog = sfeat + 128;
    float* sinv = slog + 20;
    const __half* hroot = (const __half*)(smem + BUF_SZ);
    int t = tid;
    if (t < 64) sh[t] = __half2float(hroot[t]);
    __syncthreads();
    if (t < 64) {
        float a = 0.f;
        for (int k = 0; k < 64; ++k) a += sh[k] * W1[k * 64 + t];
        sf1[t] = fmaxf(a + b1[t], 0.f);
    }
    __syncthreads();
    if (t < 64) {
        float f = 0.f;
        for (int k = 0; k < 64; ++k) f += sf1[k] * W2[k * 64 + t];
        sfeat[t] = f + b2[t];
    }
    __syncthreads();
    if (t < 64) {
        float gi = 0.f, gg = 0.f, go = 0.f;
        for (int k = 0; k < 64; ++k) {
            float fk = sfeat[k];
            gi += fk * W_ih[k * 256 + t];
            gg += fk * W_ih[k * 256 + 128 + t];
            go += fk * W_ih[k * 256 + 192 + t];
        }
        gi += b_lstm[t];
        gg += b_lstm[128 + t];
        go += b_lstm[192 + t];
        float cg = (1.f / (1.f + expf(-gi))) * tanhf(gg);
        sfeat[64 + t] = (1.f / (1.f + expf(-go))) * tanhf(cg);
    }
    __syncthreads();
    if (t < 20) {
        float l = 0.f;
        for (int dd = 0; dd < 128; ++dd) l += sfeat[dd] * actorW[dd * 20 + t];
        l = logf(vm[t]) + l * vm[t] + actorb[t] * vm[t];
        slog[t] = l / 3.0f;
    }
    __syncthreads();
    if (t == 0) {
        float mx = slog[0];
        for (int k = 1; k < 20; ++k) mx = fmaxf(mx, slog[k]);
        float s = 0.f;
        for (int k = 0; k < 20; ++k) {
            float e = expf(slog[k] - mx);
            slog[k] = e;
            s += e;
        }
        sinv[0] = 1.f / s;
    }
    __syncthreads();
    if (t < 20) out[b * 20 + t] = slog[t] * sinv[0];
}

extern "C" void kernel_launch(void* const* d_in, const int* in_sizes, int n_in,
                              void* d_out, int out_size) {
    const int*   x_idx  = (const int*)d_in[0];
    const float* vm     = (const float*)d_in[1];
    const float* Wx     = (const float*)d_in[2];
    const float* Ua     = (const float*)d_in[3];
    const float* Ub     = (const float*)d_in[4];
    const float* bt     = (const float*)d_in[5];
    const float* W_ih   = (const float*)d_in[6];
    const float* b_lstm = (const float*)d_in[8];
    const float* W1     = (const float*)d_in[9];
    const float* b1     = (const float*)d_in[10];
    const float* W2     = (const float*)d_in[11];
    const float* b2     = (const float*)d_in[12];
    const float* actorW = (const float*)d_in[13];
    const float* actorb = (const float*)d_in[14];
    float* out = (float*)d_out;

    cudaFuncSetAttribute(level10_fused, cudaFuncAttributeMaxDynamicSharedMemorySize, SMEM_TOTAL);
    cudaFuncSetAttribute(level_mma, cudaFuncAttributeMaxDynamicSharedMemorySize, SMEM_TOTAL);
    cudaFuncSetAttribute(top_mma, cudaFuncAttributeMaxDynamicSharedMemorySize, SMEM_TOTAL);

    prep_kernel<<<80, 256>>>(Ua, Ub, Wx);
    level10_fused<<<152, NT, SMEM_TOTAL>>>(x_idx, bt);
    level_mma<<<152, NT, SMEM_TOTAL>>>(9, x_idx, bt, 0, 1);
    top_mma<<<BSZ, NT, SMEM_TOTAL>>>(x_idx, bt, W1, b1, W2, b2, W_ih, b_lstm,
                                     actorW, actorb, vm, out);
}

// round 11
// speedup vs baseline: 1.5734x; 1.0948x over previous
#include <cuda_runtime.h>
#include <cuda_fp16.h>
#include <math.h>
#include <cstdint>

#define BSZ 128
#define NTREE 4095
#define NT 512

// ---- fused d10+d9 kernel smem layout
#define FA_OFF 0            // A tile 32KB (128 rows x 256B swizzled)
#define FCB_OFF 32768       // leaf c-buf 128 x 272B
#define A9_OFF 67584        // stage-2 A tile 64 rows x 256B
#define C9_OFF 83968        // stage-2 c-buf 64 x 272B (interleaved uint2)
#define FB_OFF 101376       // B frags 80KB
#define FIDX_OFF 183296     // idx: 2 slots x (128+64+...) = 2 x 1536B
#define SMEM_F 186368

// ---- top kernel smem layout (round-10, unchanged)
#define BUF_SZ 67584
#define CB_OFF 32768
#define CSTRIDE 272
#define B_OFF 135168
#define IDX_OFF 217088
#define SMEM_TOTAL 219136

__device__ __half g_h[2][(size_t)BSZ * 2048 * 64];
__device__ __half g_c[2][(size_t)BSZ * 2048 * 64];
__device__ uint32_t g_Bfrag[20480];   // f16x2 fragment-ordered U
__device__ uint32_t g_Wxb[20480];     // f16x2 Wx table [idx][g][colpair]

__device__ __forceinline__ uint32_t smem_u32(const void* p) {
    uint32_t a;
    asm("{ .reg .u64 t; cvta.to.shared.u64 t, %1; cvt.u32.u64 %0, t; }" : "=r"(a) : "l"(p));
    return a;
}
__device__ __forceinline__ __half2 tanh2(__half2 x) {
    uint32_t r, xi = *(uint32_t*)&x;
    asm("tanh.approx.f16x2 %0, %1;" : "=r"(r) : "r"(xi));
    return *(__half2*)&r;
}
__device__ __forceinline__ __half2 sig2(__half2 x) {
    const __half2 h = __float2half2_rn(0.5f);
    return __hfma2(tanh2(__hmul2(x, h)), h, h);
}
__device__ __forceinline__ void mma_f16(uint32_t d[2], uint32_t a0, uint32_t a1,
                                        uint32_t a2, uint32_t a3,
                                        uint32_t b0, uint32_t b1) {
    asm volatile(
        "mma.sync.aligned.m16n8k16.row.col.f16.f16.f16.f16 "
        "{%0,%1}, {%2,%3,%4,%5}, {%6,%7}, {%0,%1};"
        : "+r"(d[0]), "+r"(d[1])
        : "r"(a0), "r"(a1), "r"(a2), "r"(a3), "r"(b0), "r"(b1));
}

// ---------------- prep: U fragments + Wx f16 table
__global__ void prep_kernel(const float* __restrict__ Ua, const float* __restrict__ Ub,
                            const float* __restrict__ Wx) {
    int id = blockIdx.x * blockDim.x + threadIdx.x;   // 20480
    if (id >= 20480) return;
    {   // U: [g][wn][ks][lane][j]
        int j = id & 1;
        int lane = (id >> 1) & 31;
        int ks = (id >> 6) & 7;
        int wn = (id >> 9) & 7;
        int g = id >> 12;
        int k0 = ks * 16 + (lane & 3) * 2 + j * 8;
        int n = g * 64 + wn * 8 + (lane >> 2);
        float v0 = (k0 < 64) ? Ua[k0 * 320 + n] : Ub[(k0 - 64) * 320 + n];
        float v1 = (k0 + 1 < 64) ? Ua[(k0 + 1) * 320 + n] : Ub[(k0 + 1 - 64) * 320 + n];
        __half2 p = __floats2half2_rn(v0, v1);
        g_Bfrag[id] = *(uint32_t*)&p;
    }
    {   // Wx: [idx][g][jp]
        int idx = id / 160;
        int rem = id - idx * 160;
        int g = rem >> 5, jp = rem & 31;
        const float* w = Wx + idx * 320 + g * 64 + 2 * jp;
        __half2 p = __floats2half2_rn(w[0], w[1]);
        g_Wxb[id] = *(uint32_t*)&p;
    }
}

// ---------------- shared tile pieces
__device__ __forceinline__ void fill_a_noidx(char* smem, int abase,
                                             const __half* __restrict__ asrc) {
    int tid = threadIdx.x;
    const uint4* src = (const uint4*)asrc;
#pragma unroll
    for (int i = 0; i < 4; ++i) {
        int f = tid + i * NT;
        int row = f >> 4, c = f & 15;
        uint4 v = src[f];
        *(uint4*)(smem + abase + row * 256 + ((c ^ (row & 7)) << 4)) = v;
    }
}

// fused fill: leaf children h,c from Wx table; idx10/idx9 preload (double-buffered)
__device__ __forceinline__ void fill_children(char* smem,
                                              const int* __restrict__ cidx,
                                              const int* __restrict__ pidx10,
                                              const int* __restrict__ pidx9,
                                              int islot, const __half2 bbl[3]) {
    int tid = threadIdx.x;
    int lane = tid & 31, w = tid >> 5;
    const __half2* wxt = (const __half2*)g_Wxb;
#pragma unroll
    for (int it = 0; it < 16; ++it) {
        int child = w + it * 16;
        int idx = cidx[child];
        const __half2* wr = wxt + idx * 160;
        __half2 zi = __hadd2(wr[lane], bbl[0]);
        __half2 zo = __hadd2(wr[96 + lane], bbl[1]);
        __half2 zu = __hadd2(wr[128 + lane], bbl[2]);
        __half2 c2 = __hmul2(sig2(zi), tanh2(zu));
        __half2 h2 = __hmul2(sig2(zo), tanh2(c2));
        int row = child >> 1, side = child & 1;
        int chunk = side * 8 + (lane >> 2);
        int aaddr = FA_OFF + row * 256 + ((chunk ^ (row & 7)) << 4) + (lane & 3) * 4;
        *(uint32_t*)(smem + aaddr) = *(uint32_t*)&h2;
        *(uint32_t*)(smem + FCB_OFF + row * CSTRIDE + side * 128 + lane * 4) =
            *(uint32_t*)&c2;
    }
    int* ib = (int*)(smem + FIDX_OFF + islot * 1536);
    if (tid < 128) ib[tid] = pidx10[tid];
    else if (tid < 192) ib[128 + (tid - 128)] = pidx9[tid - 128];
}

__device__ __forceinline__ void do_mma(char* smem, uint32_t sA, uint32_t acc[4][5][2],
                                       int nvalid, int wm, int wn, int lane, int boff) {
    const int row_local = (lane & 7) | (((lane >> 3) & 1) << 3);
    const int hi = (lane >> 4) & 1;
#pragma unroll
    for (int ks = 0; ks < 8; ++ks) {
        uint2 bf[5];
#pragma unroll
        for (int g = 0; g < 5; ++g)
            bf[g] = *(const uint2*)(smem + boff + ((((g * 8 + wn) * 8 + ks) * 32 + lane) << 3));
        int c = ks * 2 + hi;
#pragma unroll
        for (int mfl = 0; mfl < 4; ++mfl) {
            int mf = wm * 4 + mfl;
            if (mf * 16 < nvalid) {
                uint32_t addr = sA + (mf * 16 + row_local) * 256 + ((c ^ (lane & 7)) << 4);
                uint32_t a0, a1, a2, a3;
                asm volatile("ldmatrix.sync.aligned.m8n8.x4.shared.b16 {%0,%1,%2,%3}, [%4];"
                             : "=r"(a0), "=r"(a1), "=r"(a2), "=r"(a3) : "r"(addr));
#pragma unroll
                for (int g = 0; g < 5; ++g)
                    mma_f16(acc[mfl][g], a0, a1, a2, a3, bf[g].x, bf[g].y);
            }
        }
    }
}

__device__ __forceinline__ void gates(const __half2 z[5], __half2 ca, __half2 cb,
                                      __half2& hn, __half2& cn) {
    cn = __hfma2(sig2(z[1]), ca,
          __hfma2(sig2(z[2]), cb,
           __hmul2(sig2(z[0]), tanh2(z[4]))));
    hn = __hmul2(sig2(z[3]), tanh2(cn));
}

// fused d10 epilogue: c from leaf cbuf; out -> smem A9 (swizzled) + c9 (interleaved)
__device__ __forceinline__ void epi10s(char* smem, int islot, uint32_t acc[4][5][2],
                                       const __half2 bb2[5], int wm, int jp, int lane) {
    const int* idx10 = (const int*)(smem + FIDX_OFF + islot * 1536);
#pragma unroll
    for (int mfl = 0; mfl < 4; ++mfl) {
#pragma unroll
        for (int half = 0; half < 2; ++half) {
            int rloc = wm * 64 + mfl * 16 + half * 8 + (lane >> 2);
            int idx = idx10[rloc];
            const __half2* w = (const __half2*)g_Wxb + idx * 160 + jp;
            __half2 z[5];
#pragma unroll
            for (int g = 0; g < 5; ++g)
                z[g] = __hadd2(__hadd2(*(__half2*)&acc[mfl][g][half], w[g * 32]), bb2[g]);
            __half2 ca = *(const __half2*)(smem + FCB_OFF + rloc * CSTRIDE + jp * 4);
            __half2 cb = *(const __half2*)(smem + FCB_OFF + rloc * CSTRIDE + 128 + jp * 4);
            __half2 hn, cn;
            gates(z, ca, cb, hn, cn);
            int orow = rloc >> 1, side = rloc & 1;
            int chunk = (side * 8 + (jp >> 2)) ^ (orow & 7);
            *(uint32_t*)(smem + A9_OFF + orow * 256 + (chunk << 4) + (jp & 3) * 4) =
                *(uint32_t*)&hn;
            *(uint32_t*)(smem + C9_OFF + orow * CSTRIDE + jp * 8 + side * 4) =
                *(uint32_t*)&cn;
        }
    }
}

// fused d9 epilogue: c from smem c9 (interleaved); out -> gmem d9 state
__device__ __forceinline__ void epi9g(char* smem, int islot, uint32_t acc[4][5][2],
                                      __half* __restrict__ houtp,
                                      __half* __restrict__ coutp,
                                      const __half2 bb2[5], int wm, int jp, int lane) {
    const int* idx9 = (const int*)(smem + FIDX_OFF + islot * 1536) + 128;
#pragma unroll
    for (int mfl = 0; mfl < 4; ++mfl) {
#pragma unroll
        for (int half = 0; half < 2; ++half) {
            int rloc = wm * 64 + mfl * 16 + half * 8 + (lane >> 2);
            if (rloc < 64) {
                int idx = idx9[rloc];
                const __half2* w = (const __half2*)g_Wxb + idx * 160 + jp;
                __half2 z[5];
#pragma unroll
                for (int g = 0; g < 5; ++g)
                    z[g] = __hadd2(__hadd2(*(__half2*)&acc[mfl][g][half], w[g * 32]), bb2[g]);
                uint2 v = *(const uint2*)(smem + C9_OFF + rloc * CSTRIDE + jp * 8);
                __half2 ca = *(__half2*)&v.x;
                __half2 cb = *(__half2*)&v.y;
                __half2 hn, cn;
                gates(z, ca, cb, hn, cn);
                *(uint32_t*)(houtp + (size_t)rloc * 64 + 2 * jp) = *(uint32_t*)&hn;
                *(uint32_t*)(coutp + (size_t)rloc * 64 + 2 * jp) = *(uint32_t*)&cn;
            }
        }
    }
}

// top epilogue (round-10, unchanged): out -> next-level smem A + cbuf
__device__ __forceinline__ void epi_top(char* smem, const int* __restrict__ sidx,
                                        uint32_t acc[4][5][2], int nvalid,
                                        const __half* __restrict__ csrc, int cbin,
                                        int outbase, int orow_off,
                                        const __half2 bb2[5], int wm, int jp, int lane) {
#pragma unroll
    for (int mfl = 0; mfl < 4; ++mfl) {
#pragma unroll
        for (int half = 0; half < 2; ++half) {
            int rloc = wm * 64 + mfl * 16 + half * 8 + (lane >> 2);
            if (rloc < nvalid) {
                int idx = sidx[rloc];
                const __half2* w = (const __half2*)g_Wxb + idx * 160 + jp;
                __half2 z[5];
#pragma unroll
                for (int g = 0; g < 5; ++g)
                    z[g] = __hadd2(__hadd2(*(__half2*)&acc[mfl][g][half], w[g * 32]), bb2[g]);
                __half2 ca, cb;
                if (csrc) {
                    ca = *(const __half2*)(csrc + (size_t)rloc * 128 + 2 * jp);
                    cb = *(const __half2*)(csrc + (size_t)rloc * 128 + 64 + 2 * jp);
                } else {
                    uint2 v = *(const uint2*)(smem + cbin + rloc * CSTRIDE + jp * 8);
                    ca = *(__half2*)&v.x;
                    cb = *(__half2*)&v.y;
                }
                __half2 hn, cn;
                gates(z, ca, cb, hn, cn);
                int orow = orow_off + (rloc >> 1);
                int side = rloc & 1;
                int chunk = (side * 8 + (jp >> 2)) ^ (orow & 7);
                *(uint32_t*)(smem + outbase + orow * 256 + (chunk << 4) + (jp & 3) * 4) =
                    *(uint32_t*)&hn;
                *(uint32_t*)(smem + outbase + CB_OFF + orow * CSTRIDE + jp * 8 + side * 4) =
                    *(uint32_t*)&cn;
            }
        }
    }
}

__device__ __forceinline__ void load_common(char* smem, const float* bt, __half2 bb2[5],
                                            __half2 bbl[3], int jp, int boff) {
    int tid = threadIdx.x;
    const uint4* src = (const uint4*)g_Bfrag;
    uint4* dst = (uint4*)(smem + boff);
#pragma unroll
    for (int i = 0; i < 10; ++i) dst[tid + i * NT] = src[tid + i * NT];
#pragma unroll
    for (int g = 0; g < 5; ++g) {
        float2 bv = *(const float2*)(bt + g * 64 + 2 * jp);
        bb2[g] = __floats2half2_rn(bv.x, bv.y);
    }
    int lane = tid & 31;
    const int gsel[3] = {0, 3, 4};
#pragma unroll
    for (int e = 0; e < 3; ++e) {
        float2 bv = *(const float2*)(bt + gsel[e] * 64 + 2 * lane);
        bbl[e] = __floats2half2_rn(bv.x, bv.y);
    }
}

// ---------------- fused leaf + d10 + d9: two-stage tiles, out -> gmem d9 state
__global__ void __launch_bounds__(NT, 1)
level109(const int* __restrict__ x_idx, const float* __restrict__ bt) {
    extern __shared__ char smem[];
    uint32_t sb = smem_u32(smem);
    const int tid = threadIdx.x;
    const int lane = tid & 31, wid = tid >> 5;
    const int wm = wid >> 3, wn = wid & 7;
    const int jp = wn * 4 + (lane & 3);
    __half2 bb2[5], bbl[3];
    load_common(smem, bt, bb2, bbl, jp, FB_OFF);
    __half* ho = g_h[1];
    __half* co = g_c[1];
    int q = 0;
    for (int t = blockIdx.x; t < 1024; t += gridDim.x) {
        int m0 = t << 7, b = m0 >> 10, jl0 = m0 & 1023;
        fill_children(smem, x_idx + b * NTREE + 2047 + 2 * jl0,
                      x_idx + b * NTREE + 1023 + jl0,
                      x_idx + b * NTREE + 511 + (jl0 >> 1), q, bbl);
        __syncthreads();
        uint32_t acc[4][5][2] = {};
        do_mma(smem, sb + FA_OFF, acc, 128, wm, wn, lane, FB_OFF);
        epi10s(smem, q, acc, bb2, wm, jp, lane);
        __syncthreads();
        uint32_t acc9[4][5][2] = {};
        do_mma(smem, sb + A9_OFF, acc9, 64, wm, wn, lane, FB_OFF);
        int j0 = b * 512 + (jl0 >> 1);
        epi9g(smem, q, acc9, ho + (size_t)j0 * 64, co + (size_t)j0 * 64,
              bb2, wm, jp, lane);
        q ^= 1;
    }
}

// ---------------- fused top levels d = 8..0 + head (round-10, unchanged)
__global__ void __launch_bounds__(NT, 1)
top_mma(const int* __restrict__ x_idx, const float* __restrict__ bt,
        const float* __restrict__ W1, const float* __restrict__ b1,
        const float* __restrict__ W2, const float* __restrict__ b2,
        const float* __restrict__ W_ih, const float* __restrict__ b_lstm,
        const float* __restrict__ actorW, const float* __restrict__ actorb,
        const float* __restrict__ vm, float* __restrict__ out) {
    extern __shared__ char smem[];
    uint32_t sb = smem_u32(smem);
    const int tid = threadIdx.x;
    const int lane = tid & 31, wid = tid >> 5;
    const int wm = wid >> 3, wn = wid & 7;
    const int jp = wn * 4 + (lane & 3);
    __half2 bb2[5], bbl[3];
    load_common(smem, bt, bb2, bbl, jp, B_OFF);
    int* sidx = (int*)(smem + IDX_OFF);
    const int b = blockIdx.x;
    if (tid < 511) sidx[tid] = x_idx[b * NTREE + tid];

    // ---- d = 8: two 128-row tiles from gmem d9 state; out -> smem buf1
    fill_a_noidx(smem, 0, g_h[1] + (size_t)b * 512 * 64);
    __syncthreads();
#pragma unroll
    for (int tt = 0; tt < 2; ++tt) {
        uint32_t acc[4][5][2] = {};
        do_mma(smem, sb, acc, 128, wm, wn, lane, B_OFF);
        __syncthreads();
        if (tt == 0)
            fill_a_noidx(smem, 0, g_h[1] + (size_t)(b * 512 + 256) * 64);
        epi_top(smem, sidx + 255 + tt * 128, acc, 128,
                g_c[1] + (size_t)(b * 512 + tt * 256) * 64,
                0, BUF_SZ, tt * 64, bb2, wm, jp, lane);
        __syncthreads();
    }

    // ---- levels 7..0, smem-resident
    int p = 1;
#pragma unroll
    for (int d = 7; d >= 0; --d) {
        int n = 1 << d;
        uint32_t acc[4][5][2] = {};
        do_mma(smem, sb + p * BUF_SZ, acc, n, wm, wn, lane, B_OFF);
        epi_top(smem, sidx + (n - 1), acc, n, (const __half*)0,
                p * BUF_SZ + CB_OFF, (p ^ 1) * BUF_SZ, 0, bb2, wm, jp, lane);
        __syncthreads();
        p ^= 1;
    }

    // ---- head
    float* sh = (float*)smem;
    float* sf1 = sh + 64;
    float* sfeat = sf1 + 64;
    float* slog = sfeat + 128;
    float* sinv = slog + 20;
    const __half* hroot = (const __half*)(smem + BUF_SZ);
    int t = tid;
    if (t < 64) sh[t] = __half2float(hroot[t]);
    __syncthreads();
    if (t < 64) {
        float a = 0.f;
        for (int k = 0; k < 64; ++k) a += sh[k] * W1[k * 64 + t];
        sf1[t] = fmaxf(a + b1[t], 0.f);
    }
    __syncthreads();
    if (t < 64) {
        float f = 0.f;
        for (int k = 0; k < 64; ++k) f += sf1[k] * W2[k * 64 + t];
        sfeat[t] = f + b2[t];
    }
    __syncthreads();
    if (t < 64) {
        float gi = 0.f, gg = 0.f, go = 0.f;
        for (int k = 0; k < 64; ++k) {
            float fk = sfeat[k];
            gi += fk * W_ih[k * 256 + t];
            gg += fk * W_ih[k * 256 + 128 + t];
            go += fk * W_ih[k * 256 + 192 + t];
        }
        gi += b_lstm[t];
        gg += b_lstm[128 + t];
        go += b_lstm[192 + t];
        float cg = (1.f / (1.f + expf(-gi))) * tanhf(gg);
        sfeat[64 + t] = (1.f / (1.f + expf(-go))) * tanhf(cg);
    }
    __syncthreads();
    if (t < 20) {
        float l = 0.f;
        for (int dd = 0; dd < 128; ++dd) l += sfeat[dd] * actorW[dd * 20 + t];
        l = logf(vm[t]) + l * vm[t] + actorb[t] * vm[t];
        slog[t] = l / 3.0f;
    }
    __syncthreads();
    if (t == 0) {
        float mx = slog[0];
        for (int k = 1; k < 20; ++k) mx = fmaxf(mx, slog[k]);
        float s = 0.f;
        for (int k = 0; k < 20; ++k) {
            float e = expf(slog[k] - mx);
            slog[k] = e;
            s += e;
        }
        sinv[0] = 1.f / s;
    }
    __syncthreads();
    if (t < 20) out[b * 20 + t] = slog[t] * sinv[0];
}

extern "C" void kernel_launch(void* const* d_in, const int* in_sizes, int n_in,
                              void* d_out, int out_size) {
    const int*   x_idx  = (const int*)d_in[0];
    const float* vm     = (const float*)d_in[1];
    const float* Wx     = (const float*)d_in[2];
    const float* Ua     = (const float*)d_in[3];
    const float* Ub     = (const float*)d_in[4];
    const float* bt     = (const float*)d_in[5];
    const float* W_ih   = (const float*)d_in[6];
    const float* b_lstm = (const float*)d_in[8];
    const float* W1     = (const float*)d_in[9];
    const float* b1     = (const float*)d_in[10];
    const float* W2     = (const float*)d_in[11];
    const float* b2     = (const float*)d_in[12];
    const float* actorW = (const float*)d_in[13];
    const float* actorb = (const float*)d_in[14];
    float* out = (float*)d_out;

    cudaFuncSetAttribute(level109, cudaFuncAttributeMaxDynamicSharedMemorySize, SMEM_F);
    cudaFuncSetAttribute(top_mma, cudaFuncAttributeMaxDynamicSharedMemorySize, SMEM_TOTAL);

    prep_kernel<<<80, 256>>>(Ua, Ub, Wx);
    level109<<<152, NT, SMEM_F>>>(x_idx, bt);
    top_mma<<<BSZ, NT, SMEM_TOTAL>>>(x_idx, bt, W1, b1, W2, b2, W_ih, b_lstm,
                                     actorW, actorb, vm, out);
}